// round 13
// baseline (speedup 1.0000x reference)
#include <cuda_runtime.h>
#include <cuda_fp16.h>
#include <math.h>
#include <stdint.h>

#define BB 2
#define SS 2048
#define HH 1024
#define NH 16
#define DD 64
#define HW (HH / 2)     // packed words per row

// Scratch, all fp16x2-packed words unless noted
__device__ uint32_t g_Q[(size_t)BB * NH * SS * (DD / 2)];
__device__ uint32_t g_K[(size_t)BB * NH * SS * (DD / 2)];
__device__ uint32_t g_V[(size_t)BB * NH * SS * (DD / 2)];
__device__ uint32_t g_Vt[(size_t)BB * NH * DD * (SS / 2)];  // [bh][d][keypair]
__device__ uint32_t g_Ac[(size_t)BB * SS * HW];
__device__ uint32_t g_Xqc[(size_t)BB * SS * HW];
__device__ uint32_t g_Xsc[(size_t)BB * SS * HW];
__device__ uint32_t g_Wc[(size_t)10 * HW * HH];  // [kp][n] k-pair packed

// ---------------------------------------------------------------------------
__device__ __forceinline__ uint32_t pack_h2(float a, float b) {
    __half2 h = __floats2half2_rn(a, b);
    return *reinterpret_cast<uint32_t*>(&h);
}
__device__ __forceinline__ void mma_f16(float* d, const uint32_t* a, const uint32_t* b) {
    asm volatile(
        "mma.sync.aligned.m16n8k16.row.col.f32.f16.f16.f32 "
        "{%0,%1,%2,%3}, {%4,%5,%6,%7}, {%8,%9}, {%0,%1,%2,%3};"
        : "+f"(d[0]), "+f"(d[1]), "+f"(d[2]), "+f"(d[3])
        : "r"(a[0]), "r"(a[1]), "r"(a[2]), "r"(a[3]), "r"(b[0]), "r"(b[1]));
}
__device__ __forceinline__ uint32_t smem_u32(const void* p) {
    uint32_t a;
    asm("{ .reg .u64 t; cvta.to.shared.u64 t, %1; cvt.u32.u64 %0, t; }" : "=r"(a) : "l"(p));
    return a;
}
#define CP_ASYNC(dst, src, sz) \
    asm volatile("cp.async.cg.shared.global [%0], [%1], 16, %2;" \
                 :: "r"(dst), "l"(src), "r"(sz) : "memory")
#define CP_COMMIT() asm volatile("cp.async.commit_group;" ::: "memory")
#define CP_WAIT1()  asm volatile("cp.async.wait_group 1;" ::: "memory")
#define CP_WAIT2()  asm volatile("cp.async.wait_group 2;" ::: "memory")

// ---------------------------------------------------------------------------
// fp32 -> packed fp16 conversions (q and s merged into one launch)
// ---------------------------------------------------------------------------
__global__ __launch_bounds__(256) void cvt4_2(const float* __restrict__ xq,
                                              const float* __restrict__ xs,
                                              uint32_t* __restrict__ yq,
                                              uint32_t* __restrict__ ys, int n4)
{
    const float* x = blockIdx.y ? xs : xq;
    uint32_t* y = blockIdx.y ? ys : yq;
    int i = blockIdx.x * 256 + threadIdx.x;
    if (i < n4) {
        float4 v = ((const float4*)x)[i];
        uint2 u;
        u.x = pack_h2(v.x, v.y);
        u.y = pack_h2(v.z, v.w);
        ((uint2*)y)[i] = u;
    }
}
__global__ __launch_bounds__(256) void cvt_w(
    const float* __restrict__ Wq, const float* __restrict__ Wk,
    const float* __restrict__ Wv, const float* __restrict__ Wo,
    uint32_t* __restrict__ y)
{
    int z = blockIdx.z;
    const float* src = z < 3 ? Wq + (size_t)z * HH * HH
                     : z < 6 ? Wk + (size_t)(z - 3) * HH * HH
                     : z < 9 ? Wv + (size_t)(z - 6) * HH * HH
                             : Wo;
    uint32_t* dst = y + (size_t)z * HW * HH;
    int i = blockIdx.x * 256 + threadIdx.x;
    int kp = i >> 10;
    int n = i & 1023;
    dst[i] = pack_h2(src[(size_t)(2 * kp) * HH + n],
                     src[(size_t)(2 * kp + 1) * HH + n]);
}
// V [bh][key][dp] -> Vt [bh][d][keyp]
__global__ __launch_bounds__(256) void repack_v(
    const uint32_t* __restrict__ V, uint32_t* __restrict__ Vt)
{
    __shared__ __half smh[64][66];
    const int bh = blockIdx.y;
    const int kt = blockIdx.x;
    const uint32_t* src = V + ((size_t)bh * SS + kt * 64) * (DD / 2);
    for (int f = threadIdx.x; f < 64 * 32; f += 256) {
        int key = f >> 5, w = f & 31;
        uint32_t u = src[key * 32 + w];
        __half2 h = *reinterpret_cast<__half2*>(&u);
        smh[key][w * 2] = h.x;
        smh[key][w * 2 + 1] = h.y;
    }
    __syncthreads();
    uint32_t* dst = Vt + (size_t)bh * DD * (SS / 2) + kt * 32;
    for (int f = threadIdx.x; f < 64 * 32; f += 256) {
        int d = f >> 5, kp = f & 31;
        dst[(size_t)d * (SS / 2) + kp] =
            pack_h2(__half2float(smh[2 * kp][d]), __half2float(smh[2 * kp + 1][d]));
    }
}

// ---------------------------------------------------------------------------
// cp.async 3-stage BK=32 fp16 mma GEMM with conv halo (round-12 core).
// BM=128, BN=128, 8 warps (2m x 4n), warp tile 64x32, 2 blocks/SM.
// ---------------------------------------------------------------------------
#define A_STRIDE 20
#define A_WORDS (128 * A_STRIDE)        // 2560
#define B_WORDS (16 * 128)              // 2048
#define STG_WORDS (A_WORDS + B_WORDS)   // 4608
#define STG_BYTES (STG_WORDS * 4)       // 18432
#define GEMM_DSMEM (3 * STG_BYTES)      // 55296
#define CONV_BLOCKS 296                 // 148 SMs x 2 blocks: zero-tail persistent

template <int TAPS, bool HEADS_OUT>
__device__ __forceinline__ void gemm_ca_core(
    const uint32_t* __restrict__ Xc, const uint32_t* __restrict__ Wc,
    const float* __restrict__ bias, void* __restrict__ Yv_, float scale,
    int m0, int n0)
{
    extern __shared__ uint32_t sm[];
    const uint32_t smb = smem_u32(sm);

    const int tid = threadIdx.x;
    const int wid = tid >> 5;
    const int lane = tid & 31;
    const int g = lane >> 2;
    const int tg = lane & 3;
    const int wm = wid >> 2;
    const int wn = wid & 3;
    const int batch = m0 >> 11;
    const int tb = m0 & (SS - 1);
    const int CENTER = (TAPS - 1) / 2;
    const int NIT = TAPS * 32;

    int am[2], ac4[2];
#pragma unroll
    for (int p = 0; p < 2; ++p) {
        int f = tid + p * 256;
        am[p] = f >> 2;
        ac4[p] = (f & 3) << 2;
    }
    int bkp[2], bn4[2];
#pragma unroll
    for (int p = 0; p < 2; ++p) {
        int f = tid + p * 256;
        bkp[p] = f >> 5;
        bn4[p] = (f & 31) << 2;
    }

    auto issue = [&](int it) {
        const int tap = it >> 5;
        const int kp0 = (it & 31) << 4;
        const uint32_t sb = smb + (uint32_t)(it % 3) * STG_BYTES;
        const uint32_t* wt = Wc + (size_t)tap * HW * HH;
#pragma unroll
        for (int p = 0; p < 2; ++p) {
            int srow = tb + am[p] + tap - CENTER;
            uint32_t sz = 16;
            int sr = srow;
            if (TAPS > 1) {
                sz = (srow >= 0 && srow < SS) ? 16u : 0u;
                sr = srow < 0 ? 0 : (srow >= SS ? SS - 1 : srow);
            }
            const uint32_t* srcA = Xc + ((size_t)batch * SS + sr) * HW + kp0 + ac4[p];
            CP_ASYNC(sb + (uint32_t)(am[p] * A_STRIDE + ac4[p]) * 4, srcA, sz);
        }
#pragma unroll
        for (int p = 0; p < 2; ++p) {
            const uint32_t* srcB = wt + (size_t)(kp0 + bkp[p]) * HH + n0 + bn4[p];
            uint32_t swz = (uint32_t)(bn4[p] ^ ((bkp[p] & 3) << 3));
            CP_ASYNC(sb + (A_WORDS + (uint32_t)bkp[p] * 128 + swz) * 4, srcB, 16u);
        }
    };

    float acc[4][4][4];
#pragma unroll
    for (int i = 0; i < 4; ++i)
#pragma unroll
        for (int j = 0; j < 4; ++j)
#pragma unroll
            for (int r = 0; r < 4; ++r) acc[i][j][r] = 0.f;

    issue(0); CP_COMMIT();
    issue(1); CP_COMMIT();

    for (int it = 0; it < NIT; ++it) {
        CP_WAIT1();
        __syncthreads();
        if (it + 2 < NIT) issue(it + 2);
        CP_COMMIT();

        const uint32_t* sA = sm + (it % 3) * STG_WORDS;
        const uint32_t* sB = sA + A_WORDS;
#pragma unroll
        for (int s = 0; s < 2; ++s) {
            const int kp1 = s * 8 + tg;
            const int kp2 = kp1 + 4;
            uint32_t a[4][4], b[4][2];
#pragma unroll
            for (int mt = 0; mt < 4; ++mt) {
                int mr = wm * 64 + mt * 16 + g;
                a[mt][0] = sA[mr * A_STRIDE + kp1];
                a[mt][1] = sA[(mr + 8) * A_STRIDE + kp1];
                a[mt][2] = sA[mr * A_STRIDE + kp2];
                a[mt][3] = sA[(mr + 8) * A_STRIDE + kp2];
            }
#pragma unroll
            for (int nt = 0; nt < 4; ++nt) {
                int ncx = (wn * 32 + nt * 8 + g) ^ (tg << 3);
                b[nt][0] = sB[kp1 * 128 + ncx];
                b[nt][1] = sB[kp2 * 128 + ncx];
            }
#pragma unroll
            for (int mt = 0; mt < 4; ++mt)
#pragma unroll
                for (int nt = 0; nt < 4; ++nt)
                    mma_f16(acc[mt][nt], a[mt], b[nt]);
        }
    }

#pragma unroll
    for (int mt = 0; mt < 4; ++mt)
#pragma unroll
        for (int half = 0; half < 2; ++half) {
            int m = m0 + wm * 64 + mt * 16 + g + half * 8;
            int bidx = m >> 11;
            int t = m & (SS - 1);
#pragma unroll
            for (int nt = 0; nt < 4; ++nt) {
                int n = n0 + wn * 32 + nt * 8 + tg * 2;
                float ox = (acc[mt][nt][half * 2 + 0] + bias[n + 0]) * scale;
                float oy = (acc[mt][nt][half * 2 + 1] + bias[n + 1]) * scale;
                if (HEADS_OUT) {
                    int h = n >> 6;
                    int dp = (n & 63) >> 1;
                    ((uint32_t*)Yv_)[(((size_t)bidx * NH + h) * SS + t) * (DD / 2) + dp] =
                        pack_h2(ox, oy);
                } else {
                    *(float2*)((float*)Yv_ + (size_t)m * HH + n) = make_float2(ox, oy);
                }
            }
        }
}

// Persistent conv3: 768 tiles over exactly 296 resident CTAs (no tail wave).
__global__ __launch_bounds__(256, 2) void conv3_ca(
    const uint32_t* __restrict__ Xq, const uint32_t* __restrict__ Xs,
    const uint32_t* __restrict__ Wc,
    const float* __restrict__ bq, const float* __restrict__ bk,
    const float* __restrict__ bv,
    uint32_t* __restrict__ Yq, uint32_t* __restrict__ Yk,
    uint32_t* __restrict__ Yv)
{
    for (int tile = blockIdx.x; tile < 768; tile += CONV_BLOCKS) {
        const int z = tile >> 8;          // 256 tiles per projection
        const int rem = tile & 255;
        const int m0 = (rem >> 3) * 128;  // 32 m-tiles
        const int n0 = (rem & 7) * 128;   // 8 n-tiles
        gemm_ca_core<3, true>(z ? Xs : Xq, Wc + (size_t)z * 3 * HW * HH,
                              z == 0 ? bq : (z == 1 ? bk : bv),
                              z == 0 ? Yq : (z == 1 ? Yk : Yv),
                              z == 0 ? 0.125f : 1.0f, m0, n0);
    }
}

__global__ __launch_bounds__(256, 2) void outproj_ca(
    const uint32_t* __restrict__ Xc, const uint32_t* __restrict__ Wc,
    const float* __restrict__ bias, float* __restrict__ Y)
{
    gemm_ca_core<1, false>(Xc, Wc + (size_t)9 * HW * HH, bias, Y, 1.0f,
                           blockIdx.y * 128, blockIdx.x * 128);
}

// ---------------------------------------------------------------------------
// Attention v4 (fp16 m16n8k16) — round-11 math, now 2 blocks/SM.
// ---------------------------------------------------------------------------
#define KN_W (64 * 36)
#define VT_W (64 * 36)
#define BUF_W (KN_W + VT_W)
#define MSK_OFF (4 * BUF_W)
#define ATTN_DSMEM ((MSK_OFF + SS) * 4)

__global__ __launch_bounds__(256, 2) void attn_tc(const float* __restrict__ mask,
                                                  uint32_t* __restrict__ Aout)
{
    extern __shared__ uint32_t sm[];
    const uint32_t smb = smem_u32(sm);
    float* msk = (float*)(sm + MSK_OFF);

    const int q0 = blockIdx.x * 128;
    const int h = blockIdx.y;
    const int b = blockIdx.z;
    const int tid = threadIdx.x;
    const int wid = tid >> 5;
    const int lane = tid & 31;
    const int g = lane >> 2;
    const int tg = lane & 3;
    const int bh = b * NH + h;
    const size_t basew = (size_t)bh * SS * (DD / 2);
    const int qr = q0 + wid * 16;

    for (int i = tid; i < SS; i += 256)
        msk[i] = mask[(size_t)b * SS + i] * (-1e9f);

    uint32_t qa[4][4];
    {
        const uint32_t* Qp = g_Q + basew + (size_t)(qr + g) * (DD / 2);
#pragma unroll
        for (int s = 0; s < 4; ++s) {
            qa[s][0] = Qp[8 * s + tg];
            qa[s][1] = Qp[8 * 32 + 8 * s + tg];
            qa[s][2] = Qp[8 * s + tg + 4];
            qa[s][3] = Qp[8 * 32 + 8 * s + tg + 4];
        }
    }

    int srow[2], sc4[2];
#pragma unroll
    for (int p = 0; p < 2; ++p) {
        int f = tid + p * 256;
        srow[p] = f >> 3;
        sc4[p] = (f & 7) << 2;
    }
    const uint32_t* Vtg = g_Vt + (size_t)bh * DD * (SS / 2);

    auto stage = [&](int t) {
        const int buf = t & 3;
        const int k0 = t << 6;
#pragma unroll
        for (int p = 0; p < 2; ++p) {
            CP_ASYNC(smb + (uint32_t)(buf * BUF_W + srow[p] * 36 + sc4[p]) * 4,
                     g_K + basew + (size_t)(k0 + srow[p]) * (DD / 2) + sc4[p], 16u);
            CP_ASYNC(smb + (uint32_t)(buf * BUF_W + KN_W + srow[p] * 36 + sc4[p]) * 4,
                     Vtg + (size_t)srow[p] * (SS / 2) + (k0 >> 1) + sc4[p], 16u);
        }
    };

    float oacc[8][4];
#pragma unroll
    for (int nt = 0; nt < 8; ++nt)
#pragma unroll
        for (int r = 0; r < 4; ++r) oacc[nt][r] = 0.f;
    float m0 = -1e30f, m8 = -1e30f, l0 = 0.f, l8 = 0.f;

    stage(0); CP_COMMIT();
    stage(1); CP_COMMIT();

    for (int t = 0; t < 32; ++t) {
        if (t + 2 < 32) stage(t + 2);
        CP_COMMIT();
        CP_WAIT2();
        __syncthreads();

        const uint32_t* Kb = sm + (t & 3) * BUF_W;
        const uint32_t* Vb = Kb + KN_W;
        const int k0 = t << 6;

        float sacc[8][4];
#pragma unroll
        for (int nt = 0; nt < 8; ++nt)
#pragma unroll
            for (int r = 0; r < 4; ++r) sacc[nt][r] = 0.f;
#pragma unroll
        for (int s = 0; s < 4; ++s)
#pragma unroll
            for (int nt = 0; nt < 8; ++nt) {
                uint32_t bfr[2];
                bfr[0] = Kb[(nt * 8 + g) * 36 + 8 * s + tg];
                bfr[1] = Kb[(nt * 8 + g) * 36 + 8 * s + tg + 4];
                mma_f16(sacc[nt], qa[s], bfr);
            }

#pragma unroll
        for (int nt = 0; nt < 8; ++nt) {
            float mk0 = msk[k0 + nt * 8 + 2 * tg];
            float mk1 = msk[k0 + nt * 8 + 2 * tg + 1];
            sacc[nt][0] += mk0; sacc[nt][1] += mk1;
            sacc[nt][2] += mk0; sacc[nt][3] += mk1;
        }

        float r0 = -1e30f, r8 = -1e30f;
#pragma unroll
        for (int nt = 0; nt < 8; ++nt) {
            r0 = fmaxf(r0, fmaxf(sacc[nt][0], sacc[nt][1]));
            r8 = fmaxf(r8, fmaxf(sacc[nt][2], sacc[nt][3]));
        }
        r0 = fmaxf(r0, __shfl_xor_sync(0xffffffffu, r0, 1));
        r0 = fmaxf(r0, __shfl_xor_sync(0xffffffffu, r0, 2));
        r8 = fmaxf(r8, __shfl_xor_sync(0xffffffffu, r8, 1));
        r8 = fmaxf(r8, __shfl_xor_sync(0xffffffffu, r8, 2));

        float nm0 = fmaxf(m0, r0), nm8 = fmaxf(m8, r8);
        float cr0 = __expf(m0 - nm0), cr8 = __expf(m8 - nm8);

        float s0 = 0.f, s8 = 0.f;
#pragma unroll
        for (int nt = 0; nt < 8; ++nt) {
            sacc[nt][0] = __expf(sacc[nt][0] - nm0);
            sacc[nt][1] = __expf(sacc[nt][1] - nm0);
            sacc[nt][2] = __expf(sacc[nt][2] - nm8);
            sacc[nt][3] = __expf(sacc[nt][3] - nm8);
            s0 += sacc[nt][0] + sacc[nt][1];
            s8 += sacc[nt][2] + sacc[nt][3];
        }
        s0 += __shfl_xor_sync(0xffffffffu, s0, 1);
        s0 += __shfl_xor_sync(0xffffffffu, s0, 2);
        s8 += __shfl_xor_sync(0xffffffffu, s8, 1);
        s8 += __shfl_xor_sync(0xffffffffu, s8, 2);

        l0 = l0 * cr0 + s0;
        l8 = l8 * cr8 + s8;
        m0 = nm0; m8 = nm8;

#pragma unroll
        for (int nt = 0; nt < 8; ++nt) {
            oacc[nt][0] *= cr0; oacc[nt][1] *= cr0;
            oacc[nt][2] *= cr8; oacc[nt][3] *= cr8;
        }

#pragma unroll
        for (int s = 0; s < 4; ++s) {
            uint32_t pa[4];
            pa[0] = pack_h2(sacc[2 * s][0], sacc[2 * s][1]);
            pa[1] = pack_h2(sacc[2 * s][2], sacc[2 * s][3]);
            pa[2] = pack_h2(sacc[2 * s + 1][0], sacc[2 * s + 1][1]);
            pa[3] = pack_h2(sacc[2 * s + 1][2], sacc[2 * s + 1][3]);
#pragma unroll
            for (int nt = 0; nt < 8; ++nt) {
                uint32_t bfr[2];
                bfr[0] = Vb[(nt * 8 + g) * 36 + 8 * s + tg];
                bfr[1] = Vb[(nt * 8 + g) * 36 + 8 * s + tg + 4];
                mma_f16(oacc[nt], pa, bfr);
            }
        }
    }

    const float inv0 = 1.f / l0, inv8 = 1.f / l8;
#pragma unroll
    for (int nt = 0; nt < 8; ++nt) {
        uint32_t w0 = pack_h2(oacc[nt][0] * inv0, oacc[nt][1] * inv0);
        uint32_t w8 = pack_h2(oacc[nt][2] * inv8, oacc[nt][3] * inv8);
        size_t col = (size_t)h * 32 + nt * 4 + tg;
        Aout[((size_t)b * SS + qr + g) * HW + col] = w0;
        Aout[((size_t)b * SS + qr + g + 8) * HW + col] = w8;
    }
}

// ---------------------------------------------------------------------------
extern "C" void kernel_launch(void* const* d_in, const int* in_sizes, int n_in,
                              void* d_out, int out_size)
{
    const float* qin  = (const float*)d_in[0];
    const float* src  = (const float*)d_in[1];
    const float* mask = (const float*)d_in[2];
    const float* Wq   = (const float*)d_in[3];
    const float* bq   = (const float*)d_in[4];
    const float* Wk   = (const float*)d_in[5];
    const float* bk   = (const float*)d_in[6];
    const float* Wv   = (const float*)d_in[7];
    const float* bv   = (const float*)d_in[8];
    const float* Wo   = (const float*)d_in[9];
    const float* bo   = (const float*)d_in[10];
    float* out = (float*)d_out;

    uint32_t *gQ, *gK, *gV, *gVt, *gAc, *gXq, *gXs, *gW;
    cudaGetSymbolAddress((void**)&gQ, g_Q);
    cudaGetSymbolAddress((void**)&gK, g_K);
    cudaGetSymbolAddress((void**)&gV, g_V);
    cudaGetSymbolAddress((void**)&gVt, g_Vt);
    cudaGetSymbolAddress((void**)&gAc, g_Ac);
    cudaGetSymbolAddress((void**)&gXq, g_Xqc);
    cudaGetSymbolAddress((void**)&gXs, g_Xsc);
    cudaGetSymbolAddress((void**)&gW, g_Wc);

    cudaFuncSetAttribute(conv3_ca, cudaFuncAttributeMaxDynamicSharedMemorySize,
                         GEMM_DSMEM);
    cudaFuncSetAttribute(outproj_ca, cudaFuncAttributeMaxDynamicSharedMemorySize,
                         GEMM_DSMEM);
    cudaFuncSetAttribute(attn_tc, cudaFuncAttributeMaxDynamicSharedMemorySize,
                         ATTN_DSMEM);

    const int N4 = BB * SS * HH / 4;
    dim3 gridCvt((N4 + 255) / 256, 2);
    cvt4_2<<<gridCvt, 256>>>(qin, src, gXq, gXs, N4);
    dim3 gridW(HW * HH / 256, 1, 10);
    cvt_w<<<gridW, 256>>>(Wq, Wk, Wv, Wo, gW);

    conv3_ca<<<CONV_BLOCKS, 256, GEMM_DSMEM>>>(gXq, gXs, gW, bq, bk, bv,
                                               gQ, gK, gV);

    dim3 gridR(SS / 64, BB * NH);                 // (32, 32)
    repack_v<<<gridR, 256>>>(gV, gVt);

    dim3 gridAttn(SS / 128, NH, BB);              // (16, 16, 2)
    attn_tc<<<gridAttn, 256, ATTN_DSMEM>>>(mask, gAc);

    dim3 gridO(HH / 128, (BB * SS) / 128);        // (8, 32)
    outproj_ca<<<gridO, 256, GEMM_DSMEM>>>(gAc, gW, bo, out);
}

// round 14
// speedup vs baseline: 1.0433x; 1.0433x over previous
#include <cuda_runtime.h>
#include <cuda_fp16.h>
#include <math.h>
#include <stdint.h>

#define BB 2
#define SS 2048
#define HH 1024
#define NH 16
#define DD 64
#define HW (HH / 2)     // packed words per row

// Scratch, all fp16x2-packed words unless noted
__device__ uint32_t g_Q[(size_t)BB * NH * SS * (DD / 2)];
__device__ uint32_t g_K[(size_t)BB * NH * SS * (DD / 2)];
__device__ uint32_t g_V[(size_t)BB * NH * SS * (DD / 2)];
__device__ uint32_t g_Vt[(size_t)BB * NH * DD * (SS / 2)];  // [bh][d][keypair]
__device__ uint32_t g_Ac[(size_t)BB * SS * HW];
__device__ uint32_t g_Xqc[(size_t)BB * SS * HW];
__device__ uint32_t g_Xsc[(size_t)BB * SS * HW];
__device__ uint32_t g_Wc[(size_t)10 * HW * HH];  // [kp][n] k-pair packed

// ---------------------------------------------------------------------------
__device__ __forceinline__ uint32_t pack_h2(float a, float b) {
    __half2 h = __floats2half2_rn(a, b);
    return *reinterpret_cast<uint32_t*>(&h);
}
__device__ __forceinline__ void mma_f16(float* d, const uint32_t* a, const uint32_t* b) {
    asm volatile(
        "mma.sync.aligned.m16n8k16.row.col.f32.f16.f16.f32 "
        "{%0,%1,%2,%3}, {%4,%5,%6,%7}, {%8,%9}, {%0,%1,%2,%3};"
        : "+f"(d[0]), "+f"(d[1]), "+f"(d[2]), "+f"(d[3])
        : "r"(a[0]), "r"(a[1]), "r"(a[2]), "r"(a[3]), "r"(b[0]), "r"(b[1]));
}
__device__ __forceinline__ uint32_t smem_u32(const void* p) {
    uint32_t a;
    asm("{ .reg .u64 t; cvta.to.shared.u64 t, %1; cvt.u32.u64 %0, t; }" : "=r"(a) : "l"(p));
    return a;
}
#define CP_ASYNC(dst, src, sz) \
    asm volatile("cp.async.cg.shared.global [%0], [%1], 16, %2;" \
                 :: "r"(dst), "l"(src), "r"(sz) : "memory")
#define CP_COMMIT() asm volatile("cp.async.commit_group;" ::: "memory")
#define CP_WAIT1()  asm volatile("cp.async.wait_group 1;" ::: "memory")
#define CP_WAIT2()  asm volatile("cp.async.wait_group 2;" ::: "memory")

// ---------------------------------------------------------------------------
// Merged fp32 -> packed fp16 conversion: z 0..1 = inputs, z 2..11 = weights.
// ---------------------------------------------------------------------------
__global__ __launch_bounds__(256) void cvt_all(
    const float* __restrict__ xq, const float* __restrict__ xs,
    const float* __restrict__ Wq, const float* __restrict__ Wk,
    const float* __restrict__ Wv, const float* __restrict__ Wo,
    uint32_t* __restrict__ yq, uint32_t* __restrict__ ys,
    uint32_t* __restrict__ yw)
{
    const int z = blockIdx.z;
    if (z < 2) {
        const float* x = z ? xs : xq;
        uint32_t* y = z ? ys : yq;
        // 1,048,576 uint2 outputs over 2048 blocks x 256 thr x 2 iters
#pragma unroll
        for (int r = 0; r < 2; ++r) {
            int i = (blockIdx.x + r * 2048) * 256 + threadIdx.x;
            float4 v = ((const float4*)x)[i];
            uint2 u;
            u.x = pack_h2(v.x, v.y);
            u.y = pack_h2(v.z, v.w);
            ((uint2*)y)[i] = u;
        }
    } else {
        const int w = z - 2;
        const float* src = w < 3 ? Wq + (size_t)w * HH * HH
                         : w < 6 ? Wk + (size_t)(w - 3) * HH * HH
                         : w < 9 ? Wv + (size_t)(w - 6) * HH * HH
                                 : Wo;
        uint32_t* dst = yw + (size_t)w * HW * HH;
        int i = blockIdx.x * 256 + threadIdx.x;    // over HW*HH = 524288 words
        int kp = i >> 10;
        int n = i & 1023;
        dst[i] = pack_h2(src[(size_t)(2 * kp) * HH + n],
                         src[(size_t)(2 * kp + 1) * HH + n]);
    }
}
// V [bh][key][dp] -> Vt [bh][d][keyp]
__global__ __launch_bounds__(256) void repack_v(
    const uint32_t* __restrict__ V, uint32_t* __restrict__ Vt)
{
    __shared__ __half smh[64][66];
    const int bh = blockIdx.y;
    const int kt = blockIdx.x;
    const uint32_t* src = V + ((size_t)bh * SS + kt * 64) * (DD / 2);
    for (int f = threadIdx.x; f < 64 * 32; f += 256) {
        int key = f >> 5, w = f & 31;
        uint32_t u = src[key * 32 + w];
        __half2 h = *reinterpret_cast<__half2*>(&u);
        smh[key][w * 2] = h.x;
        smh[key][w * 2 + 1] = h.y;
    }
    __syncthreads();
    uint32_t* dst = Vt + (size_t)bh * DD * (SS / 2) + kt * 32;
    for (int f = threadIdx.x; f < 64 * 32; f += 256) {
        int d = f >> 5, kp = f & 31;
        dst[(size_t)d * (SS / 2) + kp] =
            pack_h2(__half2float(smh[2 * kp][d]), __half2float(smh[2 * kp + 1][d]));
    }
}

// ---------------------------------------------------------------------------
// cp.async 3-stage BK=32 fp16 mma GEMM with conv halo (round-12 core, plain grid).
// BM=128, BN=128, 8 warps (2m x 4n), warp tile 64x32, 2 blocks/SM.
// ---------------------------------------------------------------------------
#define A_STRIDE 20
#define A_WORDS (128 * A_STRIDE)        // 2560
#define B_WORDS (16 * 128)              // 2048
#define STG_WORDS (A_WORDS + B_WORDS)   // 4608
#define STG_BYTES (STG_WORDS * 4)       // 18432
#define GEMM_DSMEM (3 * STG_BYTES)      // 55296

template <int TAPS, bool HEADS_OUT>
__device__ __forceinline__ void gemm_ca_core(
    const uint32_t* __restrict__ Xc, const uint32_t* __restrict__ Wc,
    const float* __restrict__ bias, void* __restrict__ Yv_, float scale,
    int m0, int n0)
{
    extern __shared__ uint32_t sm[];
    const uint32_t smb = smem_u32(sm);

    const int tid = threadIdx.x;
    const int wid = tid >> 5;
    const int lane = tid & 31;
    const int g = lane >> 2;
    const int tg = lane & 3;
    const int wm = wid >> 2;
    const int wn = wid & 3;
    const int batch = m0 >> 11;
    const int tb = m0 & (SS - 1);
    const int CENTER = (TAPS - 1) / 2;
    const int NIT = TAPS * 32;

    int am[2], ac4[2];
#pragma unroll
    for (int p = 0; p < 2; ++p) {
        int f = tid + p * 256;
        am[p] = f >> 2;
        ac4[p] = (f & 3) << 2;
    }
    int bkp[2], bn4[2];
#pragma unroll
    for (int p = 0; p < 2; ++p) {
        int f = tid + p * 256;
        bkp[p] = f >> 5;
        bn4[p] = (f & 31) << 2;
    }

    auto issue = [&](int it) {
        const int tap = it >> 5;
        const int kp0 = (it & 31) << 4;
        const uint32_t sb = smb + (uint32_t)(it % 3) * STG_BYTES;
        const uint32_t* wt = Wc + (size_t)tap * HW * HH;
#pragma unroll
        for (int p = 0; p < 2; ++p) {
            int srow = tb + am[p] + tap - CENTER;
            uint32_t sz = 16;
            int sr = srow;
            if (TAPS > 1) {
                sz = (srow >= 0 && srow < SS) ? 16u : 0u;
                sr = srow < 0 ? 0 : (srow >= SS ? SS - 1 : srow);
            }
            const uint32_t* srcA = Xc + ((size_t)batch * SS + sr) * HW + kp0 + ac4[p];
            CP_ASYNC(sb + (uint32_t)(am[p] * A_STRIDE + ac4[p]) * 4, srcA, sz);
        }
#pragma unroll
        for (int p = 0; p < 2; ++p) {
            const uint32_t* srcB = wt + (size_t)(kp0 + bkp[p]) * HH + n0 + bn4[p];
            uint32_t swz = (uint32_t)(bn4[p] ^ ((bkp[p] & 3) << 3));
            CP_ASYNC(sb + (A_WORDS + (uint32_t)bkp[p] * 128 + swz) * 4, srcB, 16u);
        }
    };

    float acc[4][4][4];
#pragma unroll
    for (int i = 0; i < 4; ++i)
#pragma unroll
        for (int j = 0; j < 4; ++j)
#pragma unroll
            for (int r = 0; r < 4; ++r) acc[i][j][r] = 0.f;

    issue(0); CP_COMMIT();
    issue(1); CP_COMMIT();

    for (int it = 0; it < NIT; ++it) {
        CP_WAIT1();
        __syncthreads();
        if (it + 2 < NIT) issue(it + 2);
        CP_COMMIT();

        const uint32_t* sA = sm + (it % 3) * STG_WORDS;
        const uint32_t* sB = sA + A_WORDS;
#pragma unroll
        for (int s = 0; s < 2; ++s) {
            const int kp1 = s * 8 + tg;
            const int kp2 = kp1 + 4;
            uint32_t a[4][4], b[4][2];
#pragma unroll
            for (int mt = 0; mt < 4; ++mt) {
                int mr = wm * 64 + mt * 16 + g;
                a[mt][0] = sA[mr * A_STRIDE + kp1];
                a[mt][1] = sA[(mr + 8) * A_STRIDE + kp1];
                a[mt][2] = sA[mr * A_STRIDE + kp2];
                a[mt][3] = sA[(mr + 8) * A_STRIDE + kp2];
            }
#pragma unroll
            for (int nt = 0; nt < 4; ++nt) {
                int ncx = (wn * 32 + nt * 8 + g) ^ (tg << 3);
                b[nt][0] = sB[kp1 * 128 + ncx];
                b[nt][1] = sB[kp2 * 128 + ncx];
            }
#pragma unroll
            for (int mt = 0; mt < 4; ++mt)
#pragma unroll
                for (int nt = 0; nt < 4; ++nt)
                    mma_f16(acc[mt][nt], a[mt], b[nt]);
        }
    }

#pragma unroll
    for (int mt = 0; mt < 4; ++mt)
#pragma unroll
        for (int half = 0; half < 2; ++half) {
            int m = m0 + wm * 64 + mt * 16 + g + half * 8;
            int bidx = m >> 11;
            int t = m & (SS - 1);
#pragma unroll
            for (int nt = 0; nt < 4; ++nt) {
                int n = n0 + wn * 32 + nt * 8 + tg * 2;
                float ox = (acc[mt][nt][half * 2 + 0] + bias[n + 0]) * scale;
                float oy = (acc[mt][nt][half * 2 + 1] + bias[n + 1]) * scale;
                if (HEADS_OUT) {
                    int h = n >> 6;
                    int dp = (n & 63) >> 1;
                    ((uint32_t*)Yv_)[(((size_t)bidx * NH + h) * SS + t) * (DD / 2) + dp] =
                        pack_h2(ox, oy);
                } else {
                    *(float2*)((float*)Yv_ + (size_t)m * HH + n) = make_float2(ox, oy);
                }
            }
        }
}

__global__ __launch_bounds__(256, 2) void conv3_ca(
    const uint32_t* __restrict__ Xq, const uint32_t* __restrict__ Xs,
    const uint32_t* __restrict__ Wc,
    const float* __restrict__ bq, const float* __restrict__ bk,
    const float* __restrict__ bv,
    uint32_t* __restrict__ Yq, uint32_t* __restrict__ Yk,
    uint32_t* __restrict__ Yv)
{
    const int z = blockIdx.z;
    gemm_ca_core<3, true>(z ? Xs : Xq, Wc + (size_t)z * 3 * HW * HH,
                          z == 0 ? bq : (z == 1 ? bk : bv),
                          z == 0 ? Yq : (z == 1 ? Yk : Yv),
                          z == 0 ? 0.125f : 1.0f,
                          blockIdx.y * 128, blockIdx.x * 128);
}

__global__ __launch_bounds__(256, 2) void outproj_ca(
    const uint32_t* __restrict__ Xc, const uint32_t* __restrict__ Wc,
    const float* __restrict__ bias, float* __restrict__ Y)
{
    gemm_ca_core<1, false>(Xc, Wc + (size_t)9 * HW * HH, bias, Y, 1.0f,
                           blockIdx.y * 128, blockIdx.x * 128);
}

// ---------------------------------------------------------------------------
// Attention v4 (fp16 m16n8k16), 2 blocks/SM (kept from round 13).
// ---------------------------------------------------------------------------
#define KN_W (64 * 36)
#define VT_W (64 * 36)
#define BUF_W (KN_W + VT_W)
#define MSK_OFF (4 * BUF_W)
#define ATTN_DSMEM ((MSK_OFF + SS) * 4)

__global__ __launch_bounds__(256, 2) void attn_tc(const float* __restrict__ mask,
                                                  uint32_t* __restrict__ Aout)
{
    extern __shared__ uint32_t sm[];
    const uint32_t smb = smem_u32(sm);
    float* msk = (float*)(sm + MSK_OFF);

    const int q0 = blockIdx.x * 128;
    const int h = blockIdx.y;
    const int b = blockIdx.z;
    const int tid = threadIdx.x;
    const int wid = tid >> 5;
    const int lane = tid & 31;
    const int g = lane >> 2;
    const int tg = lane & 3;
    const int bh = b * NH + h;
    const size_t basew = (size_t)bh * SS * (DD / 2);
    const int qr = q0 + wid * 16;

    for (int i = tid; i < SS; i += 256)
        msk[i] = mask[(size_t)b * SS + i] * (-1e9f);

    uint32_t qa[4][4];
    {
        const uint32_t* Qp = g_Q + basew + (size_t)(qr + g) * (DD / 2);
#pragma unroll
        for (int s = 0; s < 4; ++s) {
            qa[s][0] = Qp[8 * s + tg];
            qa[s][1] = Qp[8 * 32 + 8 * s + tg];
            qa[s][2] = Qp[8 * s + tg + 4];
            qa[s][3] = Qp[8 * 32 + 8 * s + tg + 4];
        }
    }

    int srow[2], sc4[2];
#pragma unroll
    for (int p = 0; p < 2; ++p) {
        int f = tid + p * 256;
        srow[p] = f >> 3;
        sc4[p] = (f & 7) << 2;
    }
    const uint32_t* Vtg = g_Vt + (size_t)bh * DD * (SS / 2);

    auto stage = [&](int t) {
        const int buf = t & 3;
        const int k0 = t << 6;
#pragma unroll
        for (int p = 0; p < 2; ++p) {
            CP_ASYNC(smb + (uint32_t)(buf * BUF_W + srow[p] * 36 + sc4[p]) * 4,
                     g_K + basew + (size_t)(k0 + srow[p]) * (DD / 2) + sc4[p], 16u);
            CP_ASYNC(smb + (uint32_t)(buf * BUF_W + KN_W + srow[p] * 36 + sc4[p]) * 4,
                     Vtg + (size_t)srow[p] * (SS / 2) + (k0 >> 1) + sc4[p], 16u);
        }
    };

    float oacc[8][4];
#pragma unroll
    for (int nt = 0; nt < 8; ++nt)
#pragma unroll
        for (int r = 0; r < 4; ++r) oacc[nt][r] = 0.f;
    float m0 = -1e30f, m8 = -1e30f, l0 = 0.f, l8 = 0.f;

    stage(0); CP_COMMIT();
    stage(1); CP_COMMIT();

    for (int t = 0; t < 32; ++t) {
        if (t + 2 < 32) stage(t + 2);
        CP_COMMIT();
        CP_WAIT2();
        __syncthreads();

        const uint32_t* Kb = sm + (t & 3) * BUF_W;
        const uint32_t* Vb = Kb + KN_W;
        const int k0 = t << 6;

        float sacc[8][4];
#pragma unroll
        for (int nt = 0; nt < 8; ++nt)
#pragma unroll
            for (int r = 0; r < 4; ++r) sacc[nt][r] = 0.f;
#pragma unroll
        for (int s = 0; s < 4; ++s)
#pragma unroll
            for (int nt = 0; nt < 8; ++nt) {
                uint32_t bfr[2];
                bfr[0] = Kb[(nt * 8 + g) * 36 + 8 * s + tg];
                bfr[1] = Kb[(nt * 8 + g) * 36 + 8 * s + tg + 4];
                mma_f16(sacc[nt], qa[s], bfr);
            }

#pragma unroll
        for (int nt = 0; nt < 8; ++nt) {
            float mk0 = msk[k0 + nt * 8 + 2 * tg];
            float mk1 = msk[k0 + nt * 8 + 2 * tg + 1];
            sacc[nt][0] += mk0; sacc[nt][1] += mk1;
            sacc[nt][2] += mk0; sacc[nt][3] += mk1;
        }

        float r0 = -1e30f, r8 = -1e30f;
#pragma unroll
        for (int nt = 0; nt < 8; ++nt) {
            r0 = fmaxf(r0, fmaxf(sacc[nt][0], sacc[nt][1]));
            r8 = fmaxf(r8, fmaxf(sacc[nt][2], sacc[nt][3]));
        }
        r0 = fmaxf(r0, __shfl_xor_sync(0xffffffffu, r0, 1));
        r0 = fmaxf(r0, __shfl_xor_sync(0xffffffffu, r0, 2));
        r8 = fmaxf(r8, __shfl_xor_sync(0xffffffffu, r8, 1));
        r8 = fmaxf(r8, __shfl_xor_sync(0xffffffffu, r8, 2));

        float nm0 = fmaxf(m0, r0), nm8 = fmaxf(m8, r8);
        float cr0 = __expf(m0 - nm0), cr8 = __expf(m8 - nm8);

        float s0 = 0.f, s8 = 0.f;
#pragma unroll
        for (int nt = 0; nt < 8; ++nt) {
            sacc[nt][0] = __expf(sacc[nt][0] - nm0);
            sacc[nt][1] = __expf(sacc[nt][1] - nm0);
            sacc[nt][2] = __expf(sacc[nt][2] - nm8);
            sacc[nt][3] = __expf(sacc[nt][3] - nm8);
            s0 += sacc[nt][0] + sacc[nt][1];
            s8 += sacc[nt][2] + sacc[nt][3];
        }
        s0 += __shfl_xor_sync(0xffffffffu, s0, 1);
        s0 += __shfl_xor_sync(0xffffffffu, s0, 2);
        s8 += __shfl_xor_sync(0xffffffffu, s8, 1);
        s8 += __shfl_xor_sync(0xffffffffu, s8, 2);

        l0 = l0 * cr0 + s0;
        l8 = l8 * cr8 + s8;
        m0 = nm0; m8 = nm8;

#pragma unroll
        for (int nt = 0; nt < 8; ++nt) {
            oacc[nt][0] *= cr0; oacc[nt][1] *= cr0;
            oacc[nt][2] *= cr8; oacc[nt][3] *= cr8;
        }

#pragma unroll
        for (int s = 0; s < 4; ++s) {
            uint32_t pa[4];
            pa[0] = pack_h2(sacc[2 * s][0], sacc[2 * s][1]);
            pa[1] = pack_h2(sacc[2 * s][2], sacc[2 * s][3]);
            pa[2] = pack_h2(sacc[2 * s + 1][0], sacc[2 * s + 1][1]);
            pa[3] = pack_h2(sacc[2 * s + 1][2], sacc[2 * s + 1][3]);
#pragma unroll
            for (int nt = 0; nt < 8; ++nt) {
                uint32_t bfr[2];
                bfr[0] = Vb[(nt * 8 + g) * 36 + 8 * s + tg];
                bfr[1] = Vb[(nt * 8 + g) * 36 + 8 * s + tg + 4];
                mma_f16(oacc[nt], pa, bfr);
            }
        }
    }

    const float inv0 = 1.f / l0, inv8 = 1.f / l8;
#pragma unroll
    for (int nt = 0; nt < 8; ++nt) {
        uint32_t w0 = pack_h2(oacc[nt][0] * inv0, oacc[nt][1] * inv0);
        uint32_t w8 = pack_h2(oacc[nt][2] * inv8, oacc[nt][3] * inv8);
        size_t col = (size_t)h * 32 + nt * 4 + tg;
        Aout[((size_t)b * SS + qr + g) * HW + col] = w0;
        Aout[((size_t)b * SS + qr + g + 8) * HW + col] = w8;
    }
}

// ---------------------------------------------------------------------------
extern "C" void kernel_launch(void* const* d_in, const int* in_sizes, int n_in,
                              void* d_out, int out_size)
{
    const float* qin  = (const float*)d_in[0];
    const float* src  = (const float*)d_in[1];
    const float* mask = (const float*)d_in[2];
    const float* Wq   = (const float*)d_in[3];
    const float* bq   = (const float*)d_in[4];
    const float* Wk   = (const float*)d_in[5];
    const float* bk   = (const float*)d_in[6];
    const float* Wv   = (const float*)d_in[7];
    const float* bv   = (const float*)d_in[8];
    const float* Wo   = (const float*)d_in[9];
    const float* bo   = (const float*)d_in[10];
    float* out = (float*)d_out;

    uint32_t *gQ, *gK, *gV, *gVt, *gAc, *gXq, *gXs, *gW;
    cudaGetSymbolAddress((void**)&gQ, g_Q);
    cudaGetSymbolAddress((void**)&gK, g_K);
    cudaGetSymbolAddress((void**)&gV, g_V);
    cudaGetSymbolAddress((void**)&gVt, g_Vt);
    cudaGetSymbolAddress((void**)&gAc, g_Ac);
    cudaGetSymbolAddress((void**)&gXq, g_Xqc);
    cudaGetSymbolAddress((void**)&gXs, g_Xsc);
    cudaGetSymbolAddress((void**)&gW, g_Wc);

    cudaFuncSetAttribute(conv3_ca, cudaFuncAttributeMaxDynamicSharedMemorySize,
                         GEMM_DSMEM);
    cudaFuncSetAttribute(outproj_ca, cudaFuncAttributeMaxDynamicSharedMemorySize,
                         GEMM_DSMEM);
    cudaFuncSetAttribute(attn_tc, cudaFuncAttributeMaxDynamicSharedMemorySize,
                         ATTN_DSMEM);

    dim3 gridCvt(2048, 1, 12);
    cvt_all<<<gridCvt, 256>>>(qin, src, Wq, Wk, Wv, Wo, gXq, gXs, gW);

    dim3 gridC(HH / 128, (BB * SS) / 128, 3);     // (8, 32, 3) — plain grid
    conv3_ca<<<gridC, 256, GEMM_DSMEM>>>(gXq, gXs, gW, bq, bk, bv, gQ, gK, gV);

    dim3 gridR(SS / 64, BB * NH);                 // (32, 32)
    repack_v<<<gridR, 256>>>(gV, gVt);

    dim3 gridAttn(SS / 128, NH, BB);              // (16, 16, 2)
    attn_tc<<<gridAttn, 256, ATTN_DSMEM>>>(mask, gAc);

    dim3 gridO(HH / 128, (BB * SS) / 128);        // (8, 32)
    outproj_ca<<<gridO, 256, GEMM_DSMEM>>>(gAc, gW, bo, out);
}

// round 15
// speedup vs baseline: 1.0687x; 1.0243x over previous
#include <cuda_runtime.h>
#include <cuda_fp16.h>
#include <math.h>
#include <stdint.h>

#define BB 2
#define SS 2048
#define HH 1024
#define NH 16
#define DD 64
#define HW (HH / 2)     // packed words per row

// Scratch, all fp16x2-packed words unless noted
__device__ uint32_t g_Q[(size_t)BB * NH * SS * (DD / 2)];
__device__ uint32_t g_K[(size_t)BB * NH * SS * (DD / 2)];
__device__ uint32_t g_V[(size_t)BB * NH * SS * (DD / 2)];
__device__ uint32_t g_Vt[(size_t)BB * NH * DD * (SS / 2)];  // [bh][d][keypair]
__device__ uint32_t g_Ac[(size_t)BB * SS * HW];
__device__ uint32_t g_Xqc[(size_t)BB * SS * HW];
__device__ uint32_t g_Xsc[(size_t)BB * SS * HW];
__device__ uint32_t g_Wc[(size_t)10 * HW * HH];  // [kp][n] k-pair packed

// ---------------------------------------------------------------------------
__device__ __forceinline__ uint32_t pack_h2(float a, float b) {
    __half2 h = __floats2half2_rn(a, b);
    return *reinterpret_cast<uint32_t*>(&h);
}
__device__ __forceinline__ void mma_f16(float* d, const uint32_t* a, const uint32_t* b) {
    asm volatile(
        "mma.sync.aligned.m16n8k16.row.col.f32.f16.f16.f32 "
        "{%0,%1,%2,%3}, {%4,%5,%6,%7}, {%8,%9}, {%0,%1,%2,%3};"
        : "+f"(d[0]), "+f"(d[1]), "+f"(d[2]), "+f"(d[3])
        : "r"(a[0]), "r"(a[1]), "r"(a[2]), "r"(a[3]), "r"(b[0]), "r"(b[1]));
}
__device__ __forceinline__ uint32_t smem_u32(const void* p) {
    uint32_t a;
    asm("{ .reg .u64 t; cvta.to.shared.u64 t, %1; cvt.u32.u64 %0, t; }" : "=r"(a) : "l"(p));
    return a;
}
#define CP_ASYNC(dst, src, sz) \
    asm volatile("cp.async.cg.shared.global [%0], [%1], 16, %2;" \
                 :: "r"(dst), "l"(src), "r"(sz) : "memory")
#define CP_COMMIT() asm volatile("cp.async.commit_group;" ::: "memory")
#define CP_WAIT1()  asm volatile("cp.async.wait_group 1;" ::: "memory")
#define CP_WAIT2()  asm volatile("cp.async.wait_group 2;" ::: "memory")

// ---------------------------------------------------------------------------
// Merged fp32 -> packed fp16 conversion: z 0..1 = inputs, z 2..11 = weights.
// Weight path fully vectorized: float4 x 2 rows -> uint4.
// ---------------------------------------------------------------------------
__global__ __launch_bounds__(256) void cvt_all(
    const float* __restrict__ xq, const float* __restrict__ xs,
    const float* __restrict__ Wq, const float* __restrict__ Wk,
    const float* __restrict__ Wv, const float* __restrict__ Wo,
    uint32_t* __restrict__ yq, uint32_t* __restrict__ ys,
    uint32_t* __restrict__ yw)
{
    const int z = blockIdx.z;
    if (z < 2) {
        const float* x = z ? xs : xq;
        uint32_t* y = z ? ys : yq;
#pragma unroll
        for (int r = 0; r < 2; ++r) {
            int i = (blockIdx.x + r * 2048) * 256 + threadIdx.x;   // 1M uint2
            float4 v = ((const float4*)x)[i];
            uint2 u;
            u.x = pack_h2(v.x, v.y);
            u.y = pack_h2(v.z, v.w);
            ((uint2*)y)[i] = u;
        }
    } else if (blockIdx.x < 512) {
        const int w = z - 2;
        const float* src = w < 3 ? Wq + (size_t)w * HH * HH
                         : w < 6 ? Wk + (size_t)(w - 3) * HH * HH
                         : w < 9 ? Wv + (size_t)(w - 6) * HH * HH
                                 : Wo;
        uint32_t* dst = yw + (size_t)w * HW * HH;
        int i4 = blockIdx.x * 256 + threadIdx.x;   // 131072 uint4 outputs
        int kp = i4 >> 8;                          // 256 uint4 per kp row
        int n4 = (i4 & 255) << 2;
        float4 r0 = *(const float4*)&src[(size_t)(2 * kp) * HH + n4];
        float4 r1 = *(const float4*)&src[(size_t)(2 * kp + 1) * HH + n4];
        uint4 o;
        o.x = pack_h2(r0.x, r1.x);
        o.y = pack_h2(r0.y, r1.y);
        o.z = pack_h2(r0.z, r1.z);
        o.w = pack_h2(r0.w, r1.w);
        *(uint4*)&dst[(size_t)kp * HH + n4] = o;
    }
}
// V [bh][key][dp] -> Vt [bh][d][keyp]
__global__ __launch_bounds__(256) void repack_v(
    const uint32_t* __restrict__ V, uint32_t* __restrict__ Vt)
{
    __shared__ __half smh[64][66];
    const int bh = blockIdx.y;
    const int kt = blockIdx.x;
    const uint32_t* src = V + ((size_t)bh * SS + kt * 64) * (DD / 2);
    for (int f = threadIdx.x; f < 64 * 32; f += 256) {
        int key = f >> 5, w = f & 31;
        uint32_t u = src[key * 32 + w];
        __half2 h = *reinterpret_cast<__half2*>(&u);
        smh[key][w * 2] = h.x;
        smh[key][w * 2 + 1] = h.y;
    }
    __syncthreads();
    uint32_t* dst = Vt + (size_t)bh * DD * (SS / 2) + kt * 32;
    for (int f = threadIdx.x; f < 64 * 32; f += 256) {
        int d = f >> 5, kp = f & 31;
        dst[(size_t)d * (SS / 2) + kp] =
            pack_h2(__half2float(smh[2 * kp][d]), __half2float(smh[2 * kp + 1][d]));
    }
}

// ---------------------------------------------------------------------------
// cp.async 3-stage BK=32 fp16 mma GEMM with conv halo (round-14 core, proven).
// BM=128, BN=128, 8 warps (2m x 4n), warp tile 64x32, 2 blocks/SM.
// ---------------------------------------------------------------------------
#define A_STRIDE 20
#define A_WORDS (128 * A_STRIDE)
#define B_WORDS (16 * 128)
#define STG_WORDS (A_WORDS + B_WORDS)
#define STG_BYTES (STG_WORDS * 4)
#define GEMM_DSMEM (3 * STG_BYTES)

template <int TAPS, bool HEADS_OUT>
__device__ __forceinline__ void gemm_ca_core(
    const uint32_t* __restrict__ Xc, const uint32_t* __restrict__ Wc,
    const float* __restrict__ bias, void* __restrict__ Yv_, float scale,
    int m0, int n0)
{
    extern __shared__ uint32_t sm[];
    const uint32_t smb = smem_u32(sm);

    const int tid = threadIdx.x;
    const int wid = tid >> 5;
    const int lane = tid & 31;
    const int g = lane >> 2;
    const int tg = lane & 3;
    const int wm = wid >> 2;
    const int wn = wid & 3;
    const int batch = m0 >> 11;
    const int tb = m0 & (SS - 1);
    const int CENTER = (TAPS - 1) / 2;
    const int NIT = TAPS * 32;

    int am[2], ac4[2];
#pragma unroll
    for (int p = 0; p < 2; ++p) {
        int f = tid + p * 256;
        am[p] = f >> 2;
        ac4[p] = (f & 3) << 2;
    }
    int bkp[2], bn4[2];
#pragma unroll
    for (int p = 0; p < 2; ++p) {
        int f = tid + p * 256;
        bkp[p] = f >> 5;
        bn4[p] = (f & 31) << 2;
    }

    auto issue = [&](int it) {
        const int tap = it >> 5;
        const int kp0 = (it & 31) << 4;
        const uint32_t sb = smb + (uint32_t)(it % 3) * STG_BYTES;
        const uint32_t* wt = Wc + (size_t)tap * HW * HH;
#pragma unroll
        for (int p = 0; p < 2; ++p) {
            int srow = tb + am[p] + tap - CENTER;
            uint32_t sz = 16;
            int sr = srow;
            if (TAPS > 1) {
                sz = (srow >= 0 && srow < SS) ? 16u : 0u;
                sr = srow < 0 ? 0 : (srow >= SS ? SS - 1 : srow);
            }
            const uint32_t* srcA = Xc + ((size_t)batch * SS + sr) * HW + kp0 + ac4[p];
            CP_ASYNC(sb + (uint32_t)(am[p] * A_STRIDE + ac4[p]) * 4, srcA, sz);
        }
#pragma unroll
        for (int p = 0; p < 2; ++p) {
            const uint32_t* srcB = wt + (size_t)(kp0 + bkp[p]) * HH + n0 + bn4[p];
            uint32_t swz = (uint32_t)(bn4[p] ^ ((bkp[p] & 3) << 3));
            CP_ASYNC(sb + (A_WORDS + (uint32_t)bkp[p] * 128 + swz) * 4, srcB, 16u);
        }
    };

    float acc[4][4][4];
#pragma unroll
    for (int i = 0; i < 4; ++i)
#pragma unroll
        for (int j = 0; j < 4; ++j)
#pragma unroll
            for (int r = 0; r < 4; ++r) acc[i][j][r] = 0.f;

    issue(0); CP_COMMIT();
    issue(1); CP_COMMIT();

    for (int it = 0; it < NIT; ++it) {
        CP_WAIT1();
        __syncthreads();
        if (it + 2 < NIT) issue(it + 2);
        CP_COMMIT();

        const uint32_t* sA = sm + (it % 3) * STG_WORDS;
        const uint32_t* sB = sA + A_WORDS;
#pragma unroll
        for (int s = 0; s < 2; ++s) {
            const int kp1 = s * 8 + tg;
            const int kp2 = kp1 + 4;
            uint32_t a[4][4], b[4][2];
#pragma unroll
            for (int mt = 0; mt < 4; ++mt) {
                int mr = wm * 64 + mt * 16 + g;
                a[mt][0] = sA[mr * A_STRIDE + kp1];
                a[mt][1] = sA[(mr + 8) * A_STRIDE + kp1];
                a[mt][2] = sA[mr * A_STRIDE + kp2];
                a[mt][3] = sA[(mr + 8) * A_STRIDE + kp2];
            }
#pragma unroll
            for (int nt = 0; nt < 4; ++nt) {
                int ncx = (wn * 32 + nt * 8 + g) ^ (tg << 3);
                b[nt][0] = sB[kp1 * 128 + ncx];
                b[nt][1] = sB[kp2 * 128 + ncx];
            }
#pragma unroll
            for (int mt = 0; mt < 4; ++mt)
#pragma unroll
                for (int nt = 0; nt < 4; ++nt)
                    mma_f16(acc[mt][nt], a[mt], b[nt]);
        }
    }

#pragma unroll
    for (int mt = 0; mt < 4; ++mt)
#pragma unroll
        for (int half = 0; half < 2; ++half) {
            int m = m0 + wm * 64 + mt * 16 + g + half * 8;
            int bidx = m >> 11;
            int t = m & (SS - 1);
#pragma unroll
            for (int nt = 0; nt < 4; ++nt) {
                int n = n0 + wn * 32 + nt * 8 + tg * 2;
                float ox = (acc[mt][nt][half * 2 + 0] + bias[n + 0]) * scale;
                float oy = (acc[mt][nt][half * 2 + 1] + bias[n + 1]) * scale;
                if (HEADS_OUT) {
                    int h = n >> 6;
                    int dp = (n & 63) >> 1;
                    ((uint32_t*)Yv_)[(((size_t)bidx * NH + h) * SS + t) * (DD / 2) + dp] =
                        pack_h2(ox, oy);
                } else {
                    *(float2*)((float*)Yv_ + (size_t)m * HH + n) = make_float2(ox, oy);
                }
            }
        }
}

__global__ __launch_bounds__(256, 2) void conv3_ca(
    const uint32_t* __restrict__ Xq, const uint32_t* __restrict__ Xs,
    const uint32_t* __restrict__ Wc,
    const float* __restrict__ bq, const float* __restrict__ bk,
    const float* __restrict__ bv,
    uint32_t* __restrict__ Yq, uint32_t* __restrict__ Yk,
    uint32_t* __restrict__ Yv)
{
    const int z = blockIdx.z;
    gemm_ca_core<3, true>(z ? Xs : Xq, Wc + (size_t)z * 3 * HW * HH,
                          z == 0 ? bq : (z == 1 ? bk : bv),
                          z == 0 ? Yq : (z == 1 ? Yk : Yv),
                          z == 0 ? 0.125f : 1.0f,
                          blockIdx.y * 128, blockIdx.x * 128);
}

__global__ __launch_bounds__(256, 2) void outproj_ca(
    const uint32_t* __restrict__ Xc, const uint32_t* __restrict__ Wc,
    const float* __restrict__ bias, float* __restrict__ Y)
{
    gemm_ca_core<1, false>(Xc, Wc + (size_t)9 * HW * HH, bias, Y, 1.0f,
                           blockIdx.y * 128, blockIdx.x * 128);
}

// ---------------------------------------------------------------------------
// Attention v5: f16x2 packed-exp softmax (ex2.approx.f16x2).
// P emerges from the exp already packed as the PV A-fragment; row sums taken
// from the same fp16 P values (self-consistent l). 2 blocks/SM.
// ---------------------------------------------------------------------------
#define KN_W (64 * 36)
#define VT_W (64 * 36)
#define BUF_W (KN_W + VT_W)
#define MSK_OFF (4 * BUF_W)
#define ATTN_DSMEM ((MSK_OFF + SS) * 4)
#define LOG2E 1.44269504f

__global__ __launch_bounds__(256, 2) void attn_tc(const float* __restrict__ mask,
                                                  uint32_t* __restrict__ Aout)
{
    extern __shared__ uint32_t sm[];
    const uint32_t smb = smem_u32(sm);
    float* msk = (float*)(sm + MSK_OFF);

    const int q0 = blockIdx.x * 128;
    const int h = blockIdx.y;
    const int b = blockIdx.z;
    const int tid = threadIdx.x;
    const int wid = tid >> 5;
    const int lane = tid & 31;
    const int g = lane >> 2;
    const int tg = lane & 3;
    const int bh = b * NH + h;
    const size_t basew = (size_t)bh * SS * (DD / 2);
    const int qr = q0 + wid * 16;

    for (int i = tid; i < SS; i += 256)
        msk[i] = mask[(size_t)b * SS + i] * (-1e9f);

    uint32_t qa[4][4];
    {
        const uint32_t* Qp = g_Q + basew + (size_t)(qr + g) * (DD / 2);
#pragma unroll
        for (int s = 0; s < 4; ++s) {
            qa[s][0] = Qp[8 * s + tg];
            qa[s][1] = Qp[8 * 32 + 8 * s + tg];
            qa[s][2] = Qp[8 * s + tg + 4];
            qa[s][3] = Qp[8 * 32 + 8 * s + tg + 4];
        }
    }

    int srow[2], sc4[2];
#pragma unroll
    for (int p = 0; p < 2; ++p) {
        int f = tid + p * 256;
        srow[p] = f >> 3;
        sc4[p] = (f & 7) << 2;
    }
    const uint32_t* Vtg = g_Vt + (size_t)bh * DD * (SS / 2);

    auto stage = [&](int t) {
        const int buf = t & 3;
        const int k0 = t << 6;
#pragma unroll
        for (int p = 0; p < 2; ++p) {
            CP_ASYNC(smb + (uint32_t)(buf * BUF_W + srow[p] * 36 + sc4[p]) * 4,
                     g_K + basew + (size_t)(k0 + srow[p]) * (DD / 2) + sc4[p], 16u);
            CP_ASYNC(smb + (uint32_t)(buf * BUF_W + KN_W + srow[p] * 36 + sc4[p]) * 4,
                     Vtg + (size_t)srow[p] * (SS / 2) + (k0 >> 1) + sc4[p], 16u);
        }
    };

    float oacc[8][4];
#pragma unroll
    for (int nt = 0; nt < 8; ++nt)
#pragma unroll
        for (int r = 0; r < 4; ++r) oacc[nt][r] = 0.f;
    float m0 = -1e30f, m8 = -1e30f, l0 = 0.f, l8 = 0.f;

    stage(0); CP_COMMIT();
    stage(1); CP_COMMIT();

    for (int t = 0; t < 32; ++t) {
        if (t + 2 < 32) stage(t + 2);
        CP_COMMIT();
        CP_WAIT2();
        __syncthreads();

        const uint32_t* Kb = sm + (t & 3) * BUF_W;
        const uint32_t* Vb = Kb + KN_W;
        const int k0 = t << 6;

        float sacc[8][4];
#pragma unroll
        for (int nt = 0; nt < 8; ++nt)
#pragma unroll
            for (int r = 0; r < 4; ++r) sacc[nt][r] = 0.f;
#pragma unroll
        for (int s = 0; s < 4; ++s)
#pragma unroll
            for (int nt = 0; nt < 8; ++nt) {
                uint32_t bfr[2];
                bfr[0] = Kb[(nt * 8 + g) * 36 + 8 * s + tg];
                bfr[1] = Kb[(nt * 8 + g) * 36 + 8 * s + tg + 4];
                mma_f16(sacc[nt], qa[s], bfr);
            }

#pragma unroll
        for (int nt = 0; nt < 8; ++nt) {
            float mk0 = msk[k0 + nt * 8 + 2 * tg];
            float mk1 = msk[k0 + nt * 8 + 2 * tg + 1];
            sacc[nt][0] += mk0; sacc[nt][1] += mk1;
            sacc[nt][2] += mk0; sacc[nt][3] += mk1;
        }

        float r0 = -1e30f, r8 = -1e30f;
#pragma unroll
        for (int nt = 0; nt < 8; ++nt) {
            r0 = fmaxf(r0, fmaxf(sacc[nt][0], sacc[nt][1]));
            r8 = fmaxf(r8, fmaxf(sacc[nt][2], sacc[nt][3]));
        }
        r0 = fmaxf(r0, __shfl_xor_sync(0xffffffffu, r0, 1));
        r0 = fmaxf(r0, __shfl_xor_sync(0xffffffffu, r0, 2));
        r8 = fmaxf(r8, __shfl_xor_sync(0xffffffffu, r8, 1));
        r8 = fmaxf(r8, __shfl_xor_sync(0xffffffffu, r8, 2));

        float nm0 = fmaxf(m0, r0), nm8 = fmaxf(m8, r8);
        float cr0 = __expf(m0 - nm0), cr8 = __expf(m8 - nm8);
        const float nl0 = nm0 * LOG2E, nl8 = nm8 * LOG2E;

        // Packed fp16 exp: P = 2^(s*log2e - m*log2e), one ex2.f16x2 per pair.
        uint32_t hp[8], hq[8];
        float s0 = 0.f, s8 = 0.f;
#pragma unroll
        for (int nt = 0; nt < 8; ++nt) {
            float a0 = fmaf(sacc[nt][0], LOG2E, -nl0);
            float a1 = fmaf(sacc[nt][1], LOG2E, -nl0);
            float b0 = fmaf(sacc[nt][2], LOG2E, -nl8);
            float b1 = fmaf(sacc[nt][3], LOG2E, -nl8);
            uint32_t ua = pack_h2(a0, a1);
            uint32_t ub = pack_h2(b0, b1);
            asm("ex2.approx.f16x2 %0, %0;" : "+r"(ua));
            asm("ex2.approx.f16x2 %0, %0;" : "+r"(ub));
            hp[nt] = ua;
            hq[nt] = ub;
            float2 fa = __half22float2(*reinterpret_cast<__half2*>(&ua));
            float2 fb = __half22float2(*reinterpret_cast<__half2*>(&ub));
            s0 += fa.x + fa.y;
            s8 += fb.x + fb.y;
        }
        s0 += __shfl_xor_sync(0xffffffffu, s0, 1);
        s0 += __shfl_xor_sync(0xffffffffu, s0, 2);
        s8 += __shfl_xor_sync(0xffffffffu, s8, 1);
        s8 += __shfl_xor_sync(0xffffffffu, s8, 2);

        l0 = l0 * cr0 + s0;
        l8 = l8 * cr8 + s8;
        m0 = nm0; m8 = nm8;

#pragma unroll
        for (int nt = 0; nt < 8; ++nt) {
            oacc[nt][0] *= cr0; oacc[nt][1] *= cr0;
            oacc[nt][2] *= cr8; oacc[nt][3] *= cr8;
        }

        // O += P V : hp/hq ARE the A-fragments (no packs, no shuffles)
#pragma unroll
        for (int s = 0; s < 4; ++s) {
            uint32_t pa[4];
            pa[0] = hp[2 * s];
            pa[1] = hq[2 * s];
            pa[2] = hp[2 * s + 1];
            pa[3] = hq[2 * s + 1];
#pragma unroll
            for (int nt = 0; nt < 8; ++nt) {
                uint32_t bfr[2];
                bfr[0] = Vb[(nt * 8 + g) * 36 + 8 * s + tg];
                bfr[1] = Vb[(nt * 8 + g) * 36 + 8 * s + tg + 4];
                mma_f16(oacc[nt], pa, bfr);
            }
        }
    }

    const float inv0 = 1.f / l0, inv8 = 1.f / l8;
#pragma unroll
    for (int nt = 0; nt < 8; ++nt) {
        uint32_t w0 = pack_h2(oacc[nt][0] * inv0, oacc[nt][1] * inv0);
        uint32_t w8 = pack_h2(oacc[nt][2] * inv8, oacc[nt][3] * inv8);
        size_t col = (size_t)h * 32 + nt * 4 + tg;
        Aout[((size_t)b * SS + qr + g) * HW + col] = w0;
        Aout[((size_t)b * SS + qr + g + 8) * HW + col] = w8;
    }
}

// ---------------------------------------------------------------------------
extern "C" void kernel_launch(void* const* d_in, const int* in_sizes, int n_in,
                              void* d_out, int out_size)
{
    const float* qin  = (const float*)d_in[0];
    const float* src  = (const float*)d_in[1];
    const float* mask = (const float*)d_in[2];
    const float* Wq   = (const float*)d_in[3];
    const float* bq   = (const float*)d_in[4];
    const float* Wk   = (const float*)d_in[5];
    const float* bk   = (const float*)d_in[6];
    const float* Wv   = (const float*)d_in[7];
    const float* bv   = (const float*)d_in[8];
    const float* Wo   = (const float*)d_in[9];
    const float* bo   = (const float*)d_in[10];
    float* out = (float*)d_out;

    uint32_t *gQ, *gK, *gV, *gVt, *gAc, *gXq, *gXs, *gW;
    cudaGetSymbolAddress((void**)&gQ, g_Q);
    cudaGetSymbolAddress((void**)&gK, g_K);
    cudaGetSymbolAddress((void**)&gV, g_V);
    cudaGetSymbolAddress((void**)&gVt, g_Vt);
    cudaGetSymbolAddress((void**)&gAc, g_Ac);
    cudaGetSymbolAddress((void**)&gXq, g_Xqc);
    cudaGetSymbolAddress((void**)&gXs, g_Xsc);
    cudaGetSymbolAddress((void**)&gW, g_Wc);

    cudaFuncSetAttribute(conv3_ca, cudaFuncAttributeMaxDynamicSharedMemorySize,
                         GEMM_DSMEM);
    cudaFuncSetAttribute(outproj_ca, cudaFuncAttributeMaxDynamicSharedMemorySize,
                         GEMM_DSMEM);
    cudaFuncSetAttribute(attn_tc, cudaFuncAttributeMaxDynamicSharedMemorySize,
                         ATTN_DSMEM);

    dim3 gridCvt(2048, 1, 12);
    cvt_all<<<gridCvt, 256>>>(qin, src, Wq, Wk, Wv, Wo, gXq, gXs, gW);

    dim3 gridC(HH / 128, (BB * SS) / 128, 3);     // (8, 32, 3)
    conv3_ca<<<gridC, 256, GEMM_DSMEM>>>(gXq, gXs, gW, bq, bk, bv, gQ, gK, gV);

    dim3 gridR(SS / 64, BB * NH);                 // (32, 32)
    repack_v<<<gridR, 256>>>(gV, gVt);

    dim3 gridAttn(SS / 128, NH, BB);              // (16, 16, 2)
    attn_tc<<<gridAttn, 256, ATTN_DSMEM>>>(mask, gAc);

    dim3 gridO(HH / 128, (BB * SS) / 128);        // (8, 32)
    outproj_ca<<<gridO, 256, GEMM_DSMEM>>>(gAc, gW, bo, out);
}

// round 16
// speedup vs baseline: 1.0957x; 1.0253x over previous
#include <cuda_runtime.h>
#include <cuda_fp16.h>
#include <math.h>
#include <stdint.h>

#define BB 2
#define SS 2048
#define HH 1024
#define NH 16
#define DD 64
#define HW (HH / 2)     // packed words per row

// Scratch, all fp16x2-packed words unless noted
__device__ uint32_t g_Q[(size_t)BB * NH * SS * (DD / 2)];
__device__ uint32_t g_K[(size_t)BB * NH * SS * (DD / 2)];
__device__ uint32_t g_V[(size_t)BB * NH * SS * (DD / 2)];
__device__ uint32_t g_Ac[(size_t)BB * SS * HW];
__device__ uint32_t g_Xqc[(size_t)BB * SS * HW];
__device__ uint32_t g_Xsc[(size_t)BB * SS * HW];
__device__ uint32_t g_Wc[(size_t)10 * HW * HH];  // [kp][n] k-pair packed

// ---------------------------------------------------------------------------
__device__ __forceinline__ uint32_t pack_h2(float a, float b) {
    __half2 h = __floats2half2_rn(a, b);
    return *reinterpret_cast<uint32_t*>(&h);
}
__device__ __forceinline__ void mma_f16(float* d, const uint32_t* a, const uint32_t* b) {
    asm volatile(
        "mma.sync.aligned.m16n8k16.row.col.f32.f16.f16.f32 "
        "{%0,%1,%2,%3}, {%4,%5,%6,%7}, {%8,%9}, {%0,%1,%2,%3};"
        : "+f"(d[0]), "+f"(d[1]), "+f"(d[2]), "+f"(d[3])
        : "r"(a[0]), "r"(a[1]), "r"(a[2]), "r"(a[3]), "r"(b[0]), "r"(b[1]));
}
__device__ __forceinline__ void ldsm_x4_t(uint32_t& r0, uint32_t& r1,
                                          uint32_t& r2, uint32_t& r3,
                                          uint32_t addr) {
    asm volatile("ldmatrix.sync.aligned.m8n8.x4.trans.shared.b16 "
                 "{%0,%1,%2,%3}, [%4];"
                 : "=r"(r0), "=r"(r1), "=r"(r2), "=r"(r3) : "r"(addr));
}
__device__ __forceinline__ uint32_t smem_u32(const void* p) {
    uint32_t a;
    asm("{ .reg .u64 t; cvta.to.shared.u64 t, %1; cvt.u32.u64 %0, t; }" : "=r"(a) : "l"(p));
    return a;
}
#define CP_ASYNC(dst, src, sz) \
    asm volatile("cp.async.cg.shared.global [%0], [%1], 16, %2;" \
                 :: "r"(dst), "l"(src), "r"(sz) : "memory")
#define CP_COMMIT() asm volatile("cp.async.commit_group;" ::: "memory")
#define CP_WAIT1()  asm volatile("cp.async.wait_group 1;" ::: "memory")
#define CP_WAIT2()  asm volatile("cp.async.wait_group 2;" ::: "memory")

// ---------------------------------------------------------------------------
// Merged fp32 -> packed fp16 conversion: z 0..1 = inputs, z 2..11 = weights.
// ---------------------------------------------------------------------------
__global__ __launch_bounds__(256) void cvt_all(
    const float* __restrict__ xq, const float* __restrict__ xs,
    const float* __restrict__ Wq, const float* __restrict__ Wk,
    const float* __restrict__ Wv, const float* __restrict__ Wo,
    uint32_t* __restrict__ yq, uint32_t* __restrict__ ys,
    uint32_t* __restrict__ yw)
{
    const int z = blockIdx.z;
    if (z < 2) {
        const float* x = z ? xs : xq;
        uint32_t* y = z ? ys : yq;
#pragma unroll
        for (int r = 0; r < 2; ++r) {
            int i = (blockIdx.x + r * 2048) * 256 + threadIdx.x;
            float4 v = ((const float4*)x)[i];
            uint2 u;
            u.x = pack_h2(v.x, v.y);
            u.y = pack_h2(v.z, v.w);
            ((uint2*)y)[i] = u;
        }
    } else if (blockIdx.x < 512) {
        const int w = z - 2;
        const float* src = w < 3 ? Wq + (size_t)w * HH * HH
                         : w < 6 ? Wk + (size_t)(w - 3) * HH * HH
                         : w < 9 ? Wv + (size_t)(w - 6) * HH * HH
                                 : Wo;
        uint32_t* dst = yw + (size_t)w * HW * HH;
        int i4 = blockIdx.x * 256 + threadIdx.x;
        int kp = i4 >> 8;
        int n4 = (i4 & 255) << 2;
        float4 r0 = *(const float4*)&src[(size_t)(2 * kp) * HH + n4];
        float4 r1 = *(const float4*)&src[(size_t)(2 * kp + 1) * HH + n4];
        uint4 o;
        o.x = pack_h2(r0.x, r1.x);
        o.y = pack_h2(r0.y, r1.y);
        o.z = pack_h2(r0.z, r1.z);
        o.w = pack_h2(r0.w, r1.w);
        *(uint4*)&dst[(size_t)kp * HH + n4] = o;
    }
}

// ---------------------------------------------------------------------------
// cp.async 3-stage BK=32 fp16 mma GEMM with conv halo (round-14 core, proven).
// BM=128, BN=128, 8 warps (2m x 4n), warp tile 64x32, 2 blocks/SM.
// ---------------------------------------------------------------------------
#define A_STRIDE 20
#define A_WORDS (128 * A_STRIDE)
#define B_WORDS (16 * 128)
#define STG_WORDS (A_WORDS + B_WORDS)
#define STG_BYTES (STG_WORDS * 4)
#define GEMM_DSMEM (3 * STG_BYTES)

template <int TAPS, bool HEADS_OUT>
__device__ __forceinline__ void gemm_ca_core(
    const uint32_t* __restrict__ Xc, const uint32_t* __restrict__ Wc,
    const float* __restrict__ bias, void* __restrict__ Yv_, float scale,
    int m0, int n0)
{
    extern __shared__ uint32_t sm[];
    const uint32_t smb = smem_u32(sm);

    const int tid = threadIdx.x;
    const int wid = tid >> 5;
    const int lane = tid & 31;
    const int g = lane >> 2;
    const int tg = lane & 3;
    const int wm = wid >> 2;
    const int wn = wid & 3;
    const int batch = m0 >> 11;
    const int tb = m0 & (SS - 1);
    const int CENTER = (TAPS - 1) / 2;
    const int NIT = TAPS * 32;

    int am[2], ac4[2];
#pragma unroll
    for (int p = 0; p < 2; ++p) {
        int f = tid + p * 256;
        am[p] = f >> 2;
        ac4[p] = (f & 3) << 2;
    }
    int bkp[2], bn4[2];
#pragma unroll
    for (int p = 0; p < 2; ++p) {
        int f = tid + p * 256;
        bkp[p] = f >> 5;
        bn4[p] = (f & 31) << 2;
    }

    auto issue = [&](int it) {
        const int tap = it >> 5;
        const int kp0 = (it & 31) << 4;
        const uint32_t sb = smb + (uint32_t)(it % 3) * STG_BYTES;
        const uint32_t* wt = Wc + (size_t)tap * HW * HH;
#pragma unroll
        for (int p = 0; p < 2; ++p) {
            int srow = tb + am[p] + tap - CENTER;
            uint32_t sz = 16;
            int sr = srow;
            if (TAPS > 1) {
                sz = (srow >= 0 && srow < SS) ? 16u : 0u;
                sr = srow < 0 ? 0 : (srow >= SS ? SS - 1 : srow);
            }
            const uint32_t* srcA = Xc + ((size_t)batch * SS + sr) * HW + kp0 + ac4[p];
            CP_ASYNC(sb + (uint32_t)(am[p] * A_STRIDE + ac4[p]) * 4, srcA, sz);
        }
#pragma unroll
        for (int p = 0; p < 2; ++p) {
            const uint32_t* srcB = wt + (size_t)(kp0 + bkp[p]) * HH + n0 + bn4[p];
            uint32_t swz = (uint32_t)(bn4[p] ^ ((bkp[p] & 3) << 3));
            CP_ASYNC(sb + (A_WORDS + (uint32_t)bkp[p] * 128 + swz) * 4, srcB, 16u);
        }
    };

    float acc[4][4][4];
#pragma unroll
    for (int i = 0; i < 4; ++i)
#pragma unroll
        for (int j = 0; j < 4; ++j)
#pragma unroll
            for (int r = 0; r < 4; ++r) acc[i][j][r] = 0.f;

    issue(0); CP_COMMIT();
    issue(1); CP_COMMIT();

    for (int it = 0; it < NIT; ++it) {
        CP_WAIT1();
        __syncthreads();
        if (it + 2 < NIT) issue(it + 2);
        CP_COMMIT();

        const uint32_t* sA = sm + (it % 3) * STG_WORDS;
        const uint32_t* sB = sA + A_WORDS;
#pragma unroll
        for (int s = 0; s < 2; ++s) {
            const int kp1 = s * 8 + tg;
            const int kp2 = kp1 + 4;
            uint32_t a[4][4], b[4][2];
#pragma unroll
            for (int mt = 0; mt < 4; ++mt) {
                int mr = wm * 64 + mt * 16 + g;
                a[mt][0] = sA[mr * A_STRIDE + kp1];
                a[mt][1] = sA[(mr + 8) * A_STRIDE + kp1];
                a[mt][2] = sA[mr * A_STRIDE + kp2];
                a[mt][3] = sA[(mr + 8) * A_STRIDE + kp2];
            }
#pragma unroll
            for (int nt = 0; nt < 4; ++nt) {
                int ncx = (wn * 32 + nt * 8 + g) ^ (tg << 3);
                b[nt][0] = sB[kp1 * 128 + ncx];
                b[nt][1] = sB[kp2 * 128 + ncx];
            }
#pragma unroll
            for (int mt = 0; mt < 4; ++mt)
#pragma unroll
                for (int nt = 0; nt < 4; ++nt)
                    mma_f16(acc[mt][nt], a[mt], b[nt]);
        }
    }

#pragma unroll
    for (int mt = 0; mt < 4; ++mt)
#pragma unroll
        for (int half = 0; half < 2; ++half) {
            int m = m0 + wm * 64 + mt * 16 + g + half * 8;
            int bidx = m >> 11;
            int t = m & (SS - 1);
#pragma unroll
            for (int nt = 0; nt < 4; ++nt) {
                int n = n0 + wn * 32 + nt * 8 + tg * 2;
                float ox = (acc[mt][nt][half * 2 + 0] + bias[n + 0]) * scale;
                float oy = (acc[mt][nt][half * 2 + 1] + bias[n + 1]) * scale;
                if (HEADS_OUT) {
                    int h = n >> 6;
                    int dp = (n & 63) >> 1;
                    ((uint32_t*)Yv_)[(((size_t)bidx * NH + h) * SS + t) * (DD / 2) + dp] =
                        pack_h2(ox, oy);
                } else {
                    *(float2*)((float*)Yv_ + (size_t)m * HH + n) = make_float2(ox, oy);
                }
            }
        }
}

__global__ __launch_bounds__(256, 2) void conv3_ca(
    const uint32_t* __restrict__ Xq, const uint32_t* __restrict__ Xs,
    const uint32_t* __restrict__ Wc,
    const float* __restrict__ bq, const float* __restrict__ bk,
    const float* __restrict__ bv,
    uint32_t* __restrict__ Yq, uint32_t* __restrict__ Yk,
    uint32_t* __restrict__ Yv)
{
    const int z = blockIdx.z;
    gemm_ca_core<3, true>(z ? Xs : Xq, Wc + (size_t)z * 3 * HW * HH,
                          z == 0 ? bq : (z == 1 ? bk : bv),
                          z == 0 ? Yq : (z == 1 ? Yk : Yv),
                          z == 0 ? 0.125f : 1.0f,
                          blockIdx.y * 128, blockIdx.x * 128);
}

__global__ __launch_bounds__(256, 2) void outproj_ca(
    const uint32_t* __restrict__ Xc, const uint32_t* __restrict__ Wc,
    const float* __restrict__ bias, float* __restrict__ Y)
{
    gemm_ca_core<1, false>(Xc, Wc + (size_t)9 * HW * HH, bias, Y, 1.0f,
                           blockIdx.y * 128, blockIdx.x * 128);
}

// ---------------------------------------------------------------------------
// Attention v6: V staged NATURALLY [key][dp]; PV B-fragments produced by
// ldmatrix.m8n8.x4.trans (in-hardware transpose) — g_Vt and repack_v deleted.
// f16x2 packed-exp softmax (round 15). 2 blocks/SM.
// ---------------------------------------------------------------------------
#define KN_W (64 * 36)
#define VS_W (64 * 36)
#define BUF_W (KN_W + VS_W)
#define MSK_OFF (4 * BUF_W)
#define ATTN_DSMEM ((MSK_OFF + SS) * 4)
#define LOG2E 1.44269504f

__global__ __launch_bounds__(256, 2) void attn_tc(const float* __restrict__ mask,
                                                  uint32_t* __restrict__ Aout)
{
    extern __shared__ uint32_t sm[];
    const uint32_t smb = smem_u32(sm);
    float* msk = (float*)(sm + MSK_OFF);

    const int q0 = blockIdx.x * 128;
    const int h = blockIdx.y;
    const int b = blockIdx.z;
    const int tid = threadIdx.x;
    const int wid = tid >> 5;
    const int lane = tid & 31;
    const int g = lane >> 2;
    const int tg = lane & 3;
    const int bh = b * NH + h;
    const size_t basew = (size_t)bh * SS * (DD / 2);
    const int qr = q0 + wid * 16;

    for (int i = tid; i < SS; i += 256)
        msk[i] = mask[(size_t)b * SS + i] * (-1e9f);

    uint32_t qa[4][4];
    {
        const uint32_t* Qp = g_Q + basew + (size_t)(qr + g) * (DD / 2);
#pragma unroll
        for (int s = 0; s < 4; ++s) {
            qa[s][0] = Qp[8 * s + tg];
            qa[s][1] = Qp[8 * 32 + 8 * s + tg];
            qa[s][2] = Qp[8 * s + tg + 4];
            qa[s][3] = Qp[8 * 32 + 8 * s + tg + 4];
        }
    }

    int srow[2], sc4[2];
#pragma unroll
    for (int p = 0; p < 2; ++p) {
        int f = tid + p * 256;
        srow[p] = f >> 3;
        sc4[p] = (f & 7) << 2;
    }

    auto stage = [&](int t) {
        const int buf = t & 3;
        const int k0 = t << 6;
#pragma unroll
        for (int p = 0; p < 2; ++p) {
            CP_ASYNC(smb + (uint32_t)(buf * BUF_W + srow[p] * 36 + sc4[p]) * 4,
                     g_K + basew + (size_t)(k0 + srow[p]) * (DD / 2) + sc4[p], 16u);
            CP_ASYNC(smb + (uint32_t)(buf * BUF_W + KN_W + srow[p] * 36 + sc4[p]) * 4,
                     g_V + basew + (size_t)(k0 + srow[p]) * (DD / 2) + sc4[p], 16u);
        }
    };

    // per-thread ldmatrix byte offset: row = lane&7 (key), matrix = lane>>3 (d/8)
    const uint32_t vof = (uint32_t)(((lane & 7) * 36 + (lane >> 3) * 4) * 4);

    float oacc[8][4];
#pragma unroll
    for (int nt = 0; nt < 8; ++nt)
#pragma unroll
        for (int r = 0; r < 4; ++r) oacc[nt][r] = 0.f;
    float m0 = -1e30f, m8 = -1e30f, l0 = 0.f, l8 = 0.f;

    stage(0); CP_COMMIT();
    stage(1); CP_COMMIT();

    for (int t = 0; t < 32; ++t) {
        if (t + 2 < 32) stage(t + 2);
        CP_COMMIT();
        CP_WAIT2();
        __syncthreads();

        const uint32_t* Kb = sm + (t & 3) * BUF_W;
        const uint32_t vbase = smb + (uint32_t)((t & 3) * BUF_W + KN_W) * 4 + vof;
        const int k0 = t << 6;

        float sacc[8][4];
#pragma unroll
        for (int nt = 0; nt < 8; ++nt)
#pragma unroll
            for (int r = 0; r < 4; ++r) sacc[nt][r] = 0.f;
#pragma unroll
        for (int s = 0; s < 4; ++s)
#pragma unroll
            for (int nt = 0; nt < 8; ++nt) {
                uint32_t bfr[2];
                bfr[0] = Kb[(nt * 8 + g) * 36 + 8 * s + tg];
                bfr[1] = Kb[(nt * 8 + g) * 36 + 8 * s + tg + 4];
                mma_f16(sacc[nt], qa[s], bfr);
            }

#pragma unroll
        for (int nt = 0; nt < 8; ++nt) {
            float mk0 = msk[k0 + nt * 8 + 2 * tg];
            float mk1 = msk[k0 + nt * 8 + 2 * tg + 1];
            sacc[nt][0] += mk0; sacc[nt][1] += mk1;
            sacc[nt][2] += mk0; sacc[nt][3] += mk1;
        }

        float r0 = -1e30f, r8 = -1e30f;
#pragma unroll
        for (int nt = 0; nt < 8; ++nt) {
            r0 = fmaxf(r0, fmaxf(sacc[nt][0], sacc[nt][1]));
            r8 = fmaxf(r8, fmaxf(sacc[nt][2], sacc[nt][3]));
        }
        r0 = fmaxf(r0, __shfl_xor_sync(0xffffffffu, r0, 1));
        r0 = fmaxf(r0, __shfl_xor_sync(0xffffffffu, r0, 2));
        r8 = fmaxf(r8, __shfl_xor_sync(0xffffffffu, r8, 1));
        r8 = fmaxf(r8, __shfl_xor_sync(0xffffffffu, r8, 2));

        float nm0 = fmaxf(m0, r0), nm8 = fmaxf(m8, r8);
        float cr0 = __expf(m0 - nm0), cr8 = __expf(m8 - nm8);
        const float nl0 = nm0 * LOG2E, nl8 = nm8 * LOG2E;

        uint32_t hp[8], hq[8];
        float s0 = 0.f, s8 = 0.f;
#pragma unroll
        for (int nt = 0; nt < 8; ++nt) {
            float a0 = fmaf(sacc[nt][0], LOG2E, -nl0);
            float a1 = fmaf(sacc[nt][1], LOG2E, -nl0);
            float b0 = fmaf(sacc[nt][2], LOG2E, -nl8);
            float b1 = fmaf(sacc[nt][3], LOG2E, -nl8);
            uint32_t ua = pack_h2(a0, a1);
            uint32_t ub = pack_h2(b0, b1);
            asm("ex2.approx.f16x2 %0, %0;" : "+r"(ua));
            asm("ex2.approx.f16x2 %0, %0;" : "+r"(ub));
            hp[nt] = ua;
            hq[nt] = ub;
            float2 fa = __half22float2(*reinterpret_cast<__half2*>(&ua));
            float2 fb = __half22float2(*reinterpret_cast<__half2*>(&ub));
            s0 += fa.x + fa.y;
            s8 += fb.x + fb.y;
        }
        s0 += __shfl_xor_sync(0xffffffffu, s0, 1);
        s0 += __shfl_xor_sync(0xffffffffu, s0, 2);
        s8 += __shfl_xor_sync(0xffffffffu, s8, 1);
        s8 += __shfl_xor_sync(0xffffffffu, s8, 2);

        l0 = l0 * cr0 + s0;
        l8 = l8 * cr8 + s8;
        m0 = nm0; m8 = nm8;

#pragma unroll
        for (int nt = 0; nt < 8; ++nt) {
            oacc[nt][0] *= cr0; oacc[nt][1] *= cr0;
            oacc[nt][2] *= cr8; oacc[nt][3] *= cr8;
        }

        // O += P V : B-fragments via ldmatrix.trans from natural V layout.
#pragma unroll
        for (int s = 0; s < 4; ++s) {
            const uint32_t vb0 = vbase + (uint32_t)s * 2304;   // 16 rows * 144B
            uint32_t lo0, lo1, lo2, lo3;      // bfr[0], nt 0..3
            uint32_t hi0, hi1, hi2, hi3;      // bfr[0], nt 4..7
            uint32_t lu0, lu1, lu2, lu3;      // bfr[1], nt 0..3
            uint32_t hu0, hu1, hu2, hu3;      // bfr[1], nt 4..7
            ldsm_x4_t(lo0, lo1, lo2, lo3, vb0);
            ldsm_x4_t(hi0, hi1, hi2, hi3, vb0 + 64);
            ldsm_x4_t(lu0, lu1, lu2, lu3, vb0 + 1152);
            ldsm_x4_t(hu0, hu1, hu2, hu3, vb0 + 1152 + 64);

            uint32_t pa[4];
            pa[0] = hp[2 * s];
            pa[1] = hq[2 * s];
            pa[2] = hp[2 * s + 1];
            pa[3] = hq[2 * s + 1];

            uint32_t bfr[2];
            bfr[0] = lo0; bfr[1] = lu0; mma_f16(oacc[0], pa, bfr);
            bfr[0] = lo1; bfr[1] = lu1; mma_f16(oacc[1], pa, bfr);
            bfr[0] = lo2; bfr[1] = lu2; mma_f16(oacc[2], pa, bfr);
            bfr[0] = lo3; bfr[1] = lu3; mma_f16(oacc[3], pa, bfr);
            bfr[0] = hi0; bfr[1] = hu0; mma_f16(oacc[4], pa, bfr);
            bfr[0] = hi1; bfr[1] = hu1; mma_f16(oacc[5], pa, bfr);
            bfr[0] = hi2; bfr[1] = hu2; mma_f16(oacc[6], pa, bfr);
            bfr[0] = hi3; bfr[1] = hu3; mma_f16(oacc[7], pa, bfr);
        }
    }

    const float inv0 = 1.f / l0, inv8 = 1.f / l8;
#pragma unroll
    for (int nt = 0; nt < 8; ++nt) {
        uint32_t w0 = pack_h2(oacc[nt][0] * inv0, oacc[nt][1] * inv0);
        uint32_t w8 = pack_h2(oacc[nt][2] * inv8, oacc[nt][3] * inv8);
        size_t col = (size_t)h * 32 + nt * 4 + tg;
        Aout[((size_t)b * SS + qr + g) * HW + col] = w0;
        Aout[((size_t)b * SS + qr + g + 8) * HW + col] = w8;
    }
}

// ---------------------------------------------------------------------------
extern "C" void kernel_launch(void* const* d_in, const int* in_sizes, int n_in,
                              void* d_out, int out_size)
{
    const float* qin  = (const float*)d_in[0];
    const float* src  = (const float*)d_in[1];
    const float* mask = (const float*)d_in[2];
    const float* Wq   = (const float*)d_in[3];
    const float* bq   = (const float*)d_in[4];
    const float* Wk   = (const float*)d_in[5];
    const float* bk   = (const float*)d_in[6];
    const float* Wv   = (const float*)d_in[7];
    const float* bv   = (const float*)d_in[8];
    const float* Wo   = (const float*)d_in[9];
    const float* bo   = (const float*)d_in[10];
    float* out = (float*)d_out;

    uint32_t *gQ, *gK, *gV, *gAc, *gXq, *gXs, *gW;
    cudaGetSymbolAddress((void**)&gQ, g_Q);
    cudaGetSymbolAddress((void**)&gK, g_K);
    cudaGetSymbolAddress((void**)&gV, g_V);
    cudaGetSymbolAddress((void**)&gAc, g_Ac);
    cudaGetSymbolAddress((void**)&gXq, g_Xqc);
    cudaGetSymbolAddress((void**)&gXs, g_Xsc);
    cudaGetSymbolAddress((void**)&gW, g_Wc);

    cudaFuncSetAttribute(conv3_ca, cudaFuncAttributeMaxDynamicSharedMemorySize,
                         GEMM_DSMEM);
    cudaFuncSetAttribute(outproj_ca, cudaFuncAttributeMaxDynamicSharedMemorySize,
                         GEMM_DSMEM);
    cudaFuncSetAttribute(attn_tc, cudaFuncAttributeMaxDynamicSharedMemorySize,
                         ATTN_DSMEM);

    dim3 gridCvt(2048, 1, 12);
    cvt_all<<<gridCvt, 256>>>(qin, src, Wq, Wk, Wv, Wo, gXq, gXs, gW);

    dim3 gridC(HH / 128, (BB * SS) / 128, 3);     // (8, 32, 3)
    conv3_ca<<<gridC, 256, GEMM_DSMEM>>>(gXq, gXs, gW, bq, bk, bv, gQ, gK, gV);

    dim3 gridAttn(SS / 128, NH, BB);              // (16, 16, 2)
    attn_tc<<<gridAttn, 256, ATTN_DSMEM>>>(mask, gAc);

    dim3 gridO(HH / 128, (BB * SS) / 128);        // (8, 32)
    outproj_ca<<<gridO, 256, GEMM_DSMEM>>>(gAc, gW, bo, out);
}

// round 17
// speedup vs baseline: 1.1079x; 1.0111x over previous
#include <cuda_runtime.h>
#include <cuda_fp16.h>
#include <math.h>
#include <stdint.h>

#define BB 2
#define SS 2048
#define HH 1024
#define NH 16
#define DD 64
#define HW (HH / 2)     // packed words per row

// Scratch, all fp16x2-packed words unless noted
__device__ uint32_t g_Q[(size_t)BB * NH * SS * (DD / 2)];
__device__ uint32_t g_K[(size_t)BB * NH * SS * (DD / 2)];
__device__ uint32_t g_V[(size_t)BB * NH * SS * (DD / 2)];
__device__ uint32_t g_Ac[(size_t)BB * SS * HW];
__device__ uint32_t g_Xqc[(size_t)BB * SS * HW];
__device__ uint32_t g_Xsc[(size_t)BB * SS * HW];
__device__ uint32_t g_Wc[(size_t)10 * HW * HH];  // [kp][n] k-pair packed

// ---------------------------------------------------------------------------
__device__ __forceinline__ uint32_t pack_h2(float a, float b) {
    __half2 h = __floats2half2_rn(a, b);
    return *reinterpret_cast<uint32_t*>(&h);
}
__device__ __forceinline__ void mma_f16(float* d, const uint32_t* a, const uint32_t* b) {
    asm volatile(
        "mma.sync.aligned.m16n8k16.row.col.f32.f16.f16.f32 "
        "{%0,%1,%2,%3}, {%4,%5,%6,%7}, {%8,%9}, {%0,%1,%2,%3};"
        : "+f"(d[0]), "+f"(d[1]), "+f"(d[2]), "+f"(d[3])
        : "r"(a[0]), "r"(a[1]), "r"(a[2]), "r"(a[3]), "r"(b[0]), "r"(b[1]));
}
__device__ __forceinline__ void ldsm_x4_t(uint32_t& r0, uint32_t& r1,
                                          uint32_t& r2, uint32_t& r3,
                                          uint32_t addr) {
    asm volatile("ldmatrix.sync.aligned.m8n8.x4.trans.shared.b16 "
                 "{%0,%1,%2,%3}, [%4];"
                 : "=r"(r0), "=r"(r1), "=r"(r2), "=r"(r3) : "r"(addr));
}
__device__ __forceinline__ void ldsm_x4(uint32_t& r0, uint32_t& r1,
                                        uint32_t& r2, uint32_t& r3,
                                        uint32_t addr) {
    asm volatile("ldmatrix.sync.aligned.m8n8.x4.shared.b16 "
                 "{%0,%1,%2,%3}, [%4];"
                 : "=r"(r0), "=r"(r1), "=r"(r2), "=r"(r3) : "r"(addr));
}
__device__ __forceinline__ uint32_t smem_u32(const void* p) {
    uint32_t a;
    asm("{ .reg .u64 t; cvta.to.shared.u64 t, %1; cvt.u32.u64 %0, t; }" : "=r"(a) : "l"(p));
    return a;
}
#define CP_ASYNC(dst, src, sz) \
    asm volatile("cp.async.cg.shared.global [%0], [%1], 16, %2;" \
                 :: "r"(dst), "l"(src), "r"(sz) : "memory")
#define CP_COMMIT() asm volatile("cp.async.commit_group;" ::: "memory")
#define CP_WAIT1()  asm volatile("cp.async.wait_group 1;" ::: "memory")
#define CP_WAIT2()  asm volatile("cp.async.wait_group 2;" ::: "memory")

// ---------------------------------------------------------------------------
// Merged fp32 -> packed fp16 conversion: z 0..1 = inputs, z 2..11 = weights.
// ---------------------------------------------------------------------------
__global__ __launch_bounds__(256) void cvt_all(
    const float* __restrict__ xq, const float* __restrict__ xs,
    const float* __restrict__ Wq, const float* __restrict__ Wk,
    const float* __restrict__ Wv, const float* __restrict__ Wo,
    uint32_t* __restrict__ yq, uint32_t* __restrict__ ys,
    uint32_t* __restrict__ yw)
{
    const int z = blockIdx.z;
    if (z < 2) {
        const float* x = z ? xs : xq;
        uint32_t* y = z ? ys : yq;
#pragma unroll
        for (int r = 0; r < 2; ++r) {
            int i = (blockIdx.x + r * 2048) * 256 + threadIdx.x;
            float4 v = ((const float4*)x)[i];
            uint2 u;
            u.x = pack_h2(v.x, v.y);
            u.y = pack_h2(v.z, v.w);
            ((uint2*)y)[i] = u;
        }
    } else if (blockIdx.x < 512) {
        const int w = z - 2;
        const float* src = w < 3 ? Wq + (size_t)w * HH * HH
                         : w < 6 ? Wk + (size_t)(w - 3) * HH * HH
                         : w < 9 ? Wv + (size_t)(w - 6) * HH * HH
                                 : Wo;
        uint32_t* dst = yw + (size_t)w * HW * HH;
        int i4 = blockIdx.x * 256 + threadIdx.x;
        int kp = i4 >> 8;
        int n4 = (i4 & 255) << 2;
        float4 r0 = *(const float4*)&src[(size_t)(2 * kp) * HH + n4];
        float4 r1 = *(const float4*)&src[(size_t)(2 * kp + 1) * HH + n4];
        uint4 o;
        o.x = pack_h2(r0.x, r1.x);
        o.y = pack_h2(r0.y, r1.y);
        o.z = pack_h2(r0.z, r1.z);
        o.w = pack_h2(r0.w, r1.w);
        *(uint4*)&dst[(size_t)kp * HH + n4] = o;
    }
}

// ---------------------------------------------------------------------------
// cp.async 3-stage BK=32 fp16 mma GEMM with conv halo (proven core).
// BM=128, BN=128, 8 warps (2m x 4n), warp tile 64x32, 2 blocks/SM.
// ---------------------------------------------------------------------------
#define A_STRIDE 20
#define A_WORDS (128 * A_STRIDE)
#define B_WORDS (16 * 128)
#define STG_WORDS (A_WORDS + B_WORDS)
#define STG_BYTES (STG_WORDS * 4)
#define GEMM_DSMEM (3 * STG_BYTES)

template <int TAPS, bool HEADS_OUT>
__device__ __forceinline__ void gemm_ca_core(
    const uint32_t* __restrict__ Xc, const uint32_t* __restrict__ Wc,
    const float* __restrict__ bias, void* __restrict__ Yv_, float scale,
    int m0, int n0)
{
    extern __shared__ uint32_t sm[];
    const uint32_t smb = smem_u32(sm);

    const int tid = threadIdx.x;
    const int wid = tid >> 5;
    const int lane = tid & 31;
    const int g = lane >> 2;
    const int tg = lane & 3;
    const int wm = wid >> 2;
    const int wn = wid & 3;
    const int batch = m0 >> 11;
    const int tb = m0 & (SS - 1);
    const int CENTER = (TAPS - 1) / 2;
    const int NIT = TAPS * 32;

    int am[2], ac4[2];
#pragma unroll
    for (int p = 0; p < 2; ++p) {
        int f = tid + p * 256;
        am[p] = f >> 2;
        ac4[p] = (f & 3) << 2;
    }
    int bkp[2], bn4[2];
#pragma unroll
    for (int p = 0; p < 2; ++p) {
        int f = tid + p * 256;
        bkp[p] = f >> 5;
        bn4[p] = (f & 31) << 2;
    }

    auto issue = [&](int it) {
        const int tap = it >> 5;
        const int kp0 = (it & 31) << 4;
        const uint32_t sb = smb + (uint32_t)(it % 3) * STG_BYTES;
        const uint32_t* wt = Wc + (size_t)tap * HW * HH;
#pragma unroll
        for (int p = 0; p < 2; ++p) {
            int srow = tb + am[p] + tap - CENTER;
            uint32_t sz = 16;
            int sr = srow;
            if (TAPS > 1) {
                sz = (srow >= 0 && srow < SS) ? 16u : 0u;
                sr = srow < 0 ? 0 : (srow >= SS ? SS - 1 : srow);
            }
            const uint32_t* srcA = Xc + ((size_t)batch * SS + sr) * HW + kp0 + ac4[p];
            CP_ASYNC(sb + (uint32_t)(am[p] * A_STRIDE + ac4[p]) * 4, srcA, sz);
        }
#pragma unroll
        for (int p = 0; p < 2; ++p) {
            const uint32_t* srcB = wt + (size_t)(kp0 + bkp[p]) * HH + n0 + bn4[p];
            uint32_t swz = (uint32_t)(bn4[p] ^ ((bkp[p] & 3) << 3));
            CP_ASYNC(sb + (A_WORDS + (uint32_t)bkp[p] * 128 + swz) * 4, srcB, 16u);
        }
    };

    float acc[4][4][4];
#pragma unroll
    for (int i = 0; i < 4; ++i)
#pragma unroll
        for (int j = 0; j < 4; ++j)
#pragma unroll
            for (int r = 0; r < 4; ++r) acc[i][j][r] = 0.f;

    issue(0); CP_COMMIT();
    issue(1); CP_COMMIT();

    for (int it = 0; it < NIT; ++it) {
        CP_WAIT1();
        __syncthreads();
        if (it + 2 < NIT) issue(it + 2);
        CP_COMMIT();

        const uint32_t* sA = sm + (it % 3) * STG_WORDS;
        const uint32_t* sB = sA + A_WORDS;
#pragma unroll
        for (int s = 0; s < 2; ++s) {
            const int kp1 = s * 8 + tg;
            const int kp2 = kp1 + 4;
            uint32_t a[4][4], b[4][2];
#pragma unroll
            for (int mt = 0; mt < 4; ++mt) {
                int mr = wm * 64 + mt * 16 + g;
                a[mt][0] = sA[mr * A_STRIDE + kp1];
                a[mt][1] = sA[(mr + 8) * A_STRIDE + kp1];
                a[mt][2] = sA[mr * A_STRIDE + kp2];
                a[mt][3] = sA[(mr + 8) * A_STRIDE + kp2];
            }
#pragma unroll
            for (int nt = 0; nt < 4; ++nt) {
                int ncx = (wn * 32 + nt * 8 + g) ^ (tg << 3);
                b[nt][0] = sB[kp1 * 128 + ncx];
                b[nt][1] = sB[kp2 * 128 + ncx];
            }
#pragma unroll
            for (int mt = 0; mt < 4; ++mt)
#pragma unroll
                for (int nt = 0; nt < 4; ++nt)
                    mma_f16(acc[mt][nt], a[mt], b[nt]);
        }
    }

#pragma unroll
    for (int mt = 0; mt < 4; ++mt)
#pragma unroll
        for (int half = 0; half < 2; ++half) {
            int m = m0 + wm * 64 + mt * 16 + g + half * 8;
            int bidx = m >> 11;
            int t = m & (SS - 1);
#pragma unroll
            for (int nt = 0; nt < 4; ++nt) {
                int n = n0 + wn * 32 + nt * 8 + tg * 2;
                float ox = (acc[mt][nt][half * 2 + 0] + bias[n + 0]) * scale;
                float oy = (acc[mt][nt][half * 2 + 1] + bias[n + 1]) * scale;
                if (HEADS_OUT) {
                    int h = n >> 6;
                    int dp = (n & 63) >> 1;
                    ((uint32_t*)Yv_)[(((size_t)bidx * NH + h) * SS + t) * (DD / 2) + dp] =
                        pack_h2(ox, oy);
                } else {
                    *(float2*)((float*)Yv_ + (size_t)m * HH + n) = make_float2(ox, oy);
                }
            }
        }
}

__global__ __launch_bounds__(256, 2) void conv3_ca(
    const uint32_t* __restrict__ Xq, const uint32_t* __restrict__ Xs,
    const uint32_t* __restrict__ Wc,
    const float* __restrict__ bq, const float* __restrict__ bk,
    const float* __restrict__ bv,
    uint32_t* __restrict__ Yq, uint32_t* __restrict__ Yk,
    uint32_t* __restrict__ Yv)
{
    const int z = blockIdx.z;
    gemm_ca_core<3, true>(z ? Xs : Xq, Wc + (size_t)z * 3 * HW * HH,
                          z == 0 ? bq : (z == 1 ? bk : bv),
                          z == 0 ? Yq : (z == 1 ? Yk : Yv),
                          z == 0 ? 0.125f : 1.0f,
                          blockIdx.y * 128, blockIdx.x * 128);
}

__global__ __launch_bounds__(256, 2) void outproj_ca(
    const uint32_t* __restrict__ Xc, const uint32_t* __restrict__ Wc,
    const float* __restrict__ bias, float* __restrict__ Y)
{
    gemm_ca_core<1, false>(Xc, Wc + (size_t)9 * HW * HH, bias, Y, 1.0f,
                           blockIdx.y * 128, blockIdx.x * 128);
}

// ---------------------------------------------------------------------------
// Attention v7: BOTH operand streams via ldmatrix.
//   K (S-phase): non-trans ldmatrix.x4 — [key][dp] layout IS the B-fragment.
//   V (PV-phase): trans ldmatrix.x4 (round-16, proven).
// f16x2 packed-exp softmax. 2 blocks/SM. All values bit-identical to round 16.
// ---------------------------------------------------------------------------
#define KN_W (64 * 36)
#define VS_W (64 * 36)
#define BUF_W (KN_W + VS_W)
#define MSK_OFF (4 * BUF_W)
#define ATTN_DSMEM ((MSK_OFF + SS) * 4)
#define LOG2E 1.44269504f

__global__ __launch_bounds__(256, 2) void attn_tc(const float* __restrict__ mask,
                                                  uint32_t* __restrict__ Aout)
{
    extern __shared__ uint32_t sm[];
    const uint32_t smb = smem_u32(sm);
    float* msk = (float*)(sm + MSK_OFF);

    const int q0 = blockIdx.x * 128;
    const int h = blockIdx.y;
    const int b = blockIdx.z;
    const int tid = threadIdx.x;
    const int wid = tid >> 5;
    const int lane = tid & 31;
    const int g = lane >> 2;
    const int tg = lane & 3;
    const int bh = b * NH + h;
    const size_t basew = (size_t)bh * SS * (DD / 2);
    const int qr = q0 + wid * 16;

    for (int i = tid; i < SS; i += 256)
        msk[i] = mask[(size_t)b * SS + i] * (-1e9f);

    uint32_t qa[4][4];
    {
        const uint32_t* Qp = g_Q + basew + (size_t)(qr + g) * (DD / 2);
#pragma unroll
        for (int s = 0; s < 4; ++s) {
            qa[s][0] = Qp[8 * s + tg];
            qa[s][1] = Qp[8 * 32 + 8 * s + tg];
            qa[s][2] = Qp[8 * s + tg + 4];
            qa[s][3] = Qp[8 * 32 + 8 * s + tg + 4];
        }
    }

    int srow[2], sc4[2];
#pragma unroll
    for (int p = 0; p < 2; ++p) {
        int f = tid + p * 256;
        srow[p] = f >> 3;
        sc4[p] = (f & 7) << 2;
    }

    auto stage = [&](int t) {
        const int buf = t & 3;
        const int k0 = t << 6;
#pragma unroll
        for (int p = 0; p < 2; ++p) {
            CP_ASYNC(smb + (uint32_t)(buf * BUF_W + srow[p] * 36 + sc4[p]) * 4,
                     g_K + basew + (size_t)(k0 + srow[p]) * (DD / 2) + sc4[p], 16u);
            CP_ASYNC(smb + (uint32_t)(buf * BUF_W + KN_W + srow[p] * 36 + sc4[p]) * 4,
                     g_V + basew + (size_t)(k0 + srow[p]) * (DD / 2) + sc4[p], 16u);
        }
    };

    // V trans-ldmatrix offset: row = lane&7 (key), matrix = lane>>3 (d/8)
    const uint32_t vof = (uint32_t)(((lane & 7) * 36 + (lane >> 3) * 4) * 4);
    // K non-trans offset: m0/m1 = nt-even low/high d halves, m2/m3 = nt-odd
    const uint32_t kof = (uint32_t)((((lane >> 4) * 8 + (lane & 7)) * 36 +
                                     ((lane >> 3) & 1) * 4) * 4);

    float oacc[8][4];
#pragma unroll
    for (int nt = 0; nt < 8; ++nt)
#pragma unroll
        for (int r = 0; r < 4; ++r) oacc[nt][r] = 0.f;
    float m0 = -1e30f, m8 = -1e30f, l0 = 0.f, l8 = 0.f;

    stage(0); CP_COMMIT();
    stage(1); CP_COMMIT();

    for (int t = 0; t < 32; ++t) {
        if (t + 2 < 32) stage(t + 2);
        CP_COMMIT();
        CP_WAIT2();
        __syncthreads();

        const uint32_t kbase = smb + (uint32_t)((t & 3) * BUF_W) * 4 + kof;
        const uint32_t vbase = smb + (uint32_t)((t & 3) * BUF_W + KN_W) * 4 + vof;
        const int k0 = t << 6;

        // S = Q K^T : K B-fragments via non-trans ldmatrix (bit-identical)
        float sacc[8][4];
#pragma unroll
        for (int nt = 0; nt < 8; ++nt)
#pragma unroll
            for (int r = 0; r < 4; ++r) sacc[nt][r] = 0.f;
#pragma unroll
        for (int s = 0; s < 4; ++s) {
#pragma unroll
            for (int j = 0; j < 4; ++j) {       // nt pair (2j, 2j+1)
                uint32_t b0, b1, b2, b3;
                ldsm_x4(b0, b1, b2, b3, kbase + (uint32_t)j * 2304 + (uint32_t)s * 32);
                uint32_t bfr[2];
                bfr[0] = b0; bfr[1] = b1; mma_f16(sacc[2 * j],     qa[s], bfr);
                bfr[0] = b2; bfr[1] = b3; mma_f16(sacc[2 * j + 1], qa[s], bfr);
            }
        }

#pragma unroll
        for (int nt = 0; nt < 8; ++nt) {
            float mk0 = msk[k0 + nt * 8 + 2 * tg];
            float mk1 = msk[k0 + nt * 8 + 2 * tg + 1];
            sacc[nt][0] += mk0; sacc[nt][1] += mk1;
            sacc[nt][2] += mk0; sacc[nt][3] += mk1;
        }

        float r0 = -1e30f, r8 = -1e30f;
#pragma unroll
        for (int nt = 0; nt < 8; ++nt) {
            r0 = fmaxf(r0, fmaxf(sacc[nt][0], sacc[nt][1]));
            r8 = fmaxf(r8, fmaxf(sacc[nt][2], sacc[nt][3]));
        }
        r0 = fmaxf(r0, __shfl_xor_sync(0xffffffffu, r0, 1));
        r0 = fmaxf(r0, __shfl_xor_sync(0xffffffffu, r0, 2));
        r8 = fmaxf(r8, __shfl_xor_sync(0xffffffffu, r8, 1));
        r8 = fmaxf(r8, __shfl_xor_sync(0xffffffffu, r8, 2));

        float nm0 = fmaxf(m0, r0), nm8 = fmaxf(m8, r8);
        float cr0 = __expf(m0 - nm0), cr8 = __expf(m8 - nm8);
        const float nl0 = nm0 * LOG2E, nl8 = nm8 * LOG2E;

        uint32_t hp[8], hq[8];
        float s0 = 0.f, s8 = 0.f;
#pragma unroll
        for (int nt = 0; nt < 8; ++nt) {
            float a0 = fmaf(sacc[nt][0], LOG2E, -nl0);
            float a1 = fmaf(sacc[nt][1], LOG2E, -nl0);
            float b0 = fmaf(sacc[nt][2], LOG2E, -nl8);
            float b1 = fmaf(sacc[nt][3], LOG2E, -nl8);
            uint32_t ua = pack_h2(a0, a1);
            uint32_t ub = pack_h2(b0, b1);
            asm("ex2.approx.f16x2 %0, %0;" : "+r"(ua));
            asm("ex2.approx.f16x2 %0, %0;" : "+r"(ub));
            hp[nt] = ua;
            hq[nt] = ub;
            float2 fa = __half22float2(*reinterpret_cast<__half2*>(&ua));
            float2 fb = __half22float2(*reinterpret_cast<__half2*>(&ub));
            s0 += fa.x + fa.y;
            s8 += fb.x + fb.y;
        }
        s0 += __shfl_xor_sync(0xffffffffu, s0, 1);
        s0 += __shfl_xor_sync(0xffffffffu, s0, 2);
        s8 += __shfl_xor_sync(0xffffffffu, s8, 1);
        s8 += __shfl_xor_sync(0xffffffffu, s8, 2);

        l0 = l0 * cr0 + s0;
        l8 = l8 * cr8 + s8;
        m0 = nm0; m8 = nm8;

#pragma unroll
        for (int nt = 0; nt < 8; ++nt) {
            oacc[nt][0] *= cr0; oacc[nt][1] *= cr0;
            oacc[nt][2] *= cr8; oacc[nt][3] *= cr8;
        }

        // O += P V : B-fragments via ldmatrix.trans from natural V layout.
#pragma unroll
        for (int s = 0; s < 4; ++s) {
            const uint32_t vb0 = vbase + (uint32_t)s * 2304;   // 16 rows * 144B
            uint32_t lo0, lo1, lo2, lo3;
            uint32_t hi0, hi1, hi2, hi3;
            uint32_t lu0, lu1, lu2, lu3;
            uint32_t hu0, hu1, hu2, hu3;
            ldsm_x4_t(lo0, lo1, lo2, lo3, vb0);
            ldsm_x4_t(hi0, hi1, hi2, hi3, vb0 + 64);
            ldsm_x4_t(lu0, lu1, lu2, lu3, vb0 + 1152);
            ldsm_x4_t(hu0, hu1, hu2, hu3, vb0 + 1152 + 64);

            uint32_t pa[4];
            pa[0] = hp[2 * s];
            pa[1] = hq[2 * s];
            pa[2] = hp[2 * s + 1];
            pa[3] = hq[2 * s + 1];

            uint32_t bfr[2];
            bfr[0] = lo0; bfr[1] = lu0; mma_f16(oacc[0], pa, bfr);
            bfr[0] = lo1; bfr[1] = lu1; mma_f16(oacc[1], pa, bfr);
            bfr[0] = lo2; bfr[1] = lu2; mma_f16(oacc[2], pa, bfr);
            bfr[0] = lo3; bfr[1] = lu3; mma_f16(oacc[3], pa, bfr);
            bfr[0] = hi0; bfr[1] = hu0; mma_f16(oacc[4], pa, bfr);
            bfr[0] = hi1; bfr[1] = hu1; mma_f16(oacc[5], pa, bfr);
            bfr[0] = hi2; bfr[1] = hu2; mma_f16(oacc[6], pa, bfr);
            bfr[0] = hi3; bfr[1] = hu3; mma_f16(oacc[7], pa, bfr);
        }
    }

    const float inv0 = 1.f / l0, inv8 = 1.f / l8;
#pragma unroll
    for (int nt = 0; nt < 8; ++nt) {
        uint32_t w0 = pack_h2(oacc[nt][0] * inv0, oacc[nt][1] * inv0);
        uint32_t w8 = pack_h2(oacc[nt][2] * inv8, oacc[nt][3] * inv8);
        size_t col = (size_t)h * 32 + nt * 4 + tg;
        Aout[((size_t)b * SS + qr + g) * HW + col] = w0;
        Aout[((size_t)b * SS + qr + g + 8) * HW + col] = w8;
    }
}

// ---------------------------------------------------------------------------
extern "C" void kernel_launch(void* const* d_in, const int* in_sizes, int n_in,
                              void* d_out, int out_size)
{
    const float* qin  = (const float*)d_in[0];
    const float* src  = (const float*)d_in[1];
    const float* mask = (const float*)d_in[2];
    const float* Wq   = (const float*)d_in[3];
    const float* bq   = (const float*)d_in[4];
    const float* Wk   = (const float*)d_in[5];
    const float* bk   = (const float*)d_in[6];
    const float* Wv   = (const float*)d_in[7];
    const float* bv   = (const float*)d_in[8];
    const float* Wo   = (const float*)d_in[9];
    const float* bo   = (const float*)d_in[10];
    float* out = (float*)d_out;

    uint32_t *gQ, *gK, *gV, *gAc, *gXq, *gXs, *gW;
    cudaGetSymbolAddress((void**)&gQ, g_Q);
    cudaGetSymbolAddress((void**)&gK, g_K);
    cudaGetSymbolAddress((void**)&gV, g_V);
    cudaGetSymbolAddress((void**)&gAc, g_Ac);
    cudaGetSymbolAddress((void**)&gXq, g_Xqc);
    cudaGetSymbolAddress((void**)&gXs, g_Xsc);
    cudaGetSymbolAddress((void**)&gW, g_Wc);

    cudaFuncSetAttribute(conv3_ca, cudaFuncAttributeMaxDynamicSharedMemorySize,
                         GEMM_DSMEM);
    cudaFuncSetAttribute(outproj_ca, cudaFuncAttributeMaxDynamicSharedMemorySize,
                         GEMM_DSMEM);
    cudaFuncSetAttribute(attn_tc, cudaFuncAttributeMaxDynamicSharedMemorySize,
                         ATTN_DSMEM);

    dim3 gridCvt(2048, 1, 12);
    cvt_all<<<gridCvt, 256>>>(qin, src, Wq, Wk, Wv, Wo, gXq, gXs, gW);

    dim3 gridC(HH / 128, (BB * SS) / 128, 3);     // (8, 32, 3)
    conv3_ca<<<gridC, 256, GEMM_DSMEM>>>(gXq, gXs, gW, bq, bk, bv, gQ, gK, gV);

    dim3 gridAttn(SS / 128, NH, BB);              // (16, 16, 2)
    attn_tc<<<gridAttn, 256, ATTN_DSMEM>>>(mask, gAc);

    dim3 gridO(HH / 128, (BB * SS) / 128);        // (8, 32)
    outproj_ca<<<gridO, 256, GEMM_DSMEM>>>(gAc, gW, bo, out);
}